// round 1
// baseline (speedup 1.0000x reference)
#include <cuda_runtime.h>
#include <math.h>

// ---------------- problem constants ----------------
#define LAYERS 6
#define BATCH  4
#define SEQ    1024
#define DM     768
#define NH     16
#define HDIM   48
#define FFDIM  3072
#define MTOK   (BATCH*SEQ)   // 4096

// ---------------- scratch (device globals; no allocation allowed) ----------
__device__ float g_x   [MTOK*DM];        // 12.6 MB
__device__ float g_h   [MTOK*DM];
__device__ float g_qkv [MTOK*3*DM];      // 37.7 MB
__device__ float g_attn[MTOK*DM];
__device__ float g_gate[MTOK*FFDIM];     // 50.3 MB
__device__ float g_up  [MTOK*FFDIM];

// ---------------- build x = concat(cls_token, cls_tokens) -------------------
__global__ void build_x_kernel(const float* __restrict__ cls_tokens,
                               const float* __restrict__ cls_token,
                               float* __restrict__ x)
{
    int idx = blockIdx.x * blockDim.x + threadIdx.x;
    if (idx >= MTOK * DM) return;
    int row = idx / DM;
    int d   = idx - row * DM;
    int b   = row >> 10;          // /SEQ
    int s   = row & (SEQ - 1);
    float v;
    if (s == 0) v = cls_token[d];
    else        v = cls_tokens[((b * (SEQ - 1)) + (s - 1)) * DM + d];
    x[idx] = v;
}

// ---------------- layernorm over rows of 768 --------------------------------
// grid = nrows, 256 threads; in row stride configurable (final LN uses stride
// SEQ*DM to pick x[:,0,:]).
__global__ __launch_bounds__(256) void layernorm_kernel(
    const float* __restrict__ in, size_t in_stride,
    float* __restrict__ out,
    const float* __restrict__ w, const float* __restrict__ b)
{
    int row = blockIdx.x;
    const float* xr = in + (size_t)row * in_stride;
    int t = threadIdx.x;

    float v0 = xr[t], v1 = xr[t + 256], v2 = xr[t + 512];
    float s  = v0 + v1 + v2;
    float sq = v0 * v0 + v1 * v1 + v2 * v2;
    #pragma unroll
    for (int o = 16; o > 0; o >>= 1) {
        s  += __shfl_xor_sync(0xFFFFFFFFu, s,  o);
        sq += __shfl_xor_sync(0xFFFFFFFFu, sq, o);
    }
    __shared__ float ss[8], sqs[8];
    int wid = t >> 5, lane = t & 31;
    if (lane == 0) { ss[wid] = s; sqs[wid] = sq; }
    __syncthreads();
    float ts = 0.f, tq = 0.f;
    #pragma unroll
    for (int i = 0; i < 8; i++) { ts += ss[i]; tq += sqs[i]; }
    float mean = ts * (1.0f / DM);
    float var  = tq * (1.0f / DM) - mean * mean;
    float rstd = rsqrtf(var + 1e-5f);

    float* orow = out + (size_t)row * DM;
    orow[t]       = (v0 - mean) * rstd * w[t]       + b[t];
    orow[t + 256] = (v1 - mean) * rstd * w[t + 256] + b[t + 256];
    orow[t + 512] = (v2 - mean) * rstd * w[t + 512] + b[t + 512];
}

// ---------------- SGEMM: C[M,N] = (Cin +) A[M,K] @ B[N,K]^T -----------------
// All dims here are multiples of the tile sizes (M=4096, N in {768,2304,3072},
// K in {768,3072}); no bounds checks.
template <int EPI_ADD>
__global__ __launch_bounds__(256) void sgemm_nt_kernel(
    const float* __restrict__ A, const float* __restrict__ B,
    const float* __restrict__ Cin, float* __restrict__ C,
    int M, int N, int K)
{
    const int BM = 128, BN = 128, BK = 16;
    __shared__ __align__(16) float As[BK][BM];
    __shared__ __align__(16) float Bs[BK][BN];

    int bm = blockIdx.y * BM;
    int bn = blockIdx.x * BN;
    int tid = threadIdx.x;
    int tr = (tid >> 4) * 8;   // row of 8x8 micro tile
    int tc = (tid & 15) * 8;   // col of 8x8 micro tile

    float acc[8][8];
    #pragma unroll
    for (int i = 0; i < 8; i++)
        #pragma unroll
        for (int j = 0; j < 8; j++) acc[i][j] = 0.f;

    for (int k0 = 0; k0 < K; k0 += BK) {
        // load A tile: 128 rows x 16 k = 512 float4, 2 per thread
        #pragma unroll
        for (int i = 0; i < 2; i++) {
            int idx = tid * 2 + i;
            int r = idx >> 2;
            int c = (idx & 3) * 4;
            float4 v = *(const float4*)&A[(size_t)(bm + r) * K + k0 + c];
            As[c + 0][r] = v.x; As[c + 1][r] = v.y;
            As[c + 2][r] = v.z; As[c + 3][r] = v.w;
        }
        #pragma unroll
        for (int i = 0; i < 2; i++) {
            int idx = tid * 2 + i;
            int r = idx >> 2;
            int c = (idx & 3) * 4;
            float4 v = *(const float4*)&B[(size_t)(bn + r) * K + k0 + c];
            Bs[c + 0][r] = v.x; Bs[c + 1][r] = v.y;
            Bs[c + 2][r] = v.z; Bs[c + 3][r] = v.w;
        }
        __syncthreads();

        #pragma unroll
        for (int k = 0; k < BK; k++) {
            float a[8], b[8];
            *(float4*)&a[0] = *(const float4*)&As[k][tr];
            *(float4*)&a[4] = *(const float4*)&As[k][tr + 4];
            *(float4*)&b[0] = *(const float4*)&Bs[k][tc];
            *(float4*)&b[4] = *(const float4*)&Bs[k][tc + 4];
            #pragma unroll
            for (int i = 0; i < 8; i++)
                #pragma unroll
                for (int j = 0; j < 8; j++)
                    acc[i][j] = fmaf(a[i], b[j], acc[i][j]);
        }
        __syncthreads();
    }

    #pragma unroll
    for (int i = 0; i < 8; i++) {
        size_t row = (size_t)(bm + tr + i) * N + bn + tc;
        #pragma unroll
        for (int j = 0; j < 8; j += 4) {
            float4 r;
            r.x = acc[i][j + 0]; r.y = acc[i][j + 1];
            r.z = acc[i][j + 2]; r.w = acc[i][j + 3];
            if (EPI_ADD) {
                float4 cv = *(const float4*)&Cin[row + j];
                r.x += cv.x; r.y += cv.y; r.z += cv.z; r.w += cv.w;
            }
            *(float4*)&C[row + j] = r;
        }
    }
}

// ---------------- flash attention with ALiBi --------------------------------
// grid (S/128, NH, BATCH); 128 threads; each thread owns one query row.
// qkv layout: row (b*SEQ+s) of width 3*DM: [q(h,hd) | k(h,hd) | v(h,hd)].
// out layout: (b, s, h*HDIM + d) -> directly consumable by the Wo GEMM.
__global__ __launch_bounds__(128) void flash_attn_kernel(
    const float* __restrict__ qkv, const float* __restrict__ log_slopes,
    float* __restrict__ out)
{
    const int QW = 3 * DM;  // 2304
    int qt = blockIdx.x, h = blockIdx.y, b = blockIdx.z;
    int t  = threadIdx.x;
    int q_idx = qt * 128 + t;

    float slope = __expf(log_slopes[h]);
    const float scale = 0.14433756729740643f;  // 1/sqrt(48)

    const float* qrow = qkv + (size_t)(b * SEQ + q_idx) * QW + h * HDIM;
    float q[HDIM];
    #pragma unroll
    for (int d = 0; d < HDIM; d += 4) {
        float4 v = *(const float4*)(qrow + d);
        q[d] = v.x; q[d + 1] = v.y; q[d + 2] = v.z; q[d + 3] = v.w;
    }

    float o[HDIM];
    #pragma unroll
    for (int d = 0; d < HDIM; d++) o[d] = 0.f;
    float m = -INFINITY, l = 0.f;

    __shared__ __align__(16) float Ks[64][HDIM];
    __shared__ __align__(16) float Vs[64][HDIM];

    for (int kt = 0; kt < SEQ / 64; kt++) {
        __syncthreads();
        // cooperative load of 64x48 K and V tiles (float4): 768 f4 each, 6/thread
        #pragma unroll
        for (int i = 0; i < 6; i++) {
            int idx = t * 6 + i;          // 0..767
            int r = idx / 12;
            int c = (idx % 12) * 4;
            const float* krow = qkv + (size_t)(b * SEQ + kt * 64 + r) * QW
                                + DM + h * HDIM + c;
            *(float4*)&Ks[r][c] = *(const float4*)krow;
            *(float4*)&Vs[r][c] = *(const float4*)(krow + DM);
        }
        __syncthreads();

        #pragma unroll 1
        for (int j0 = 0; j0 < 64; j0 += 8) {
            float sc[8];
            #pragma unroll
            for (int jj = 0; jj < 8; jj++) {
                const float* kr = &Ks[j0 + jj][0];
                float a0 = 0.f, a1 = 0.f, a2 = 0.f, a3 = 0.f;
                #pragma unroll
                for (int d = 0; d < HDIM; d += 4) {
                    float4 kv = *(const float4*)(kr + d);
                    a0 = fmaf(q[d + 0], kv.x, a0);
                    a1 = fmaf(q[d + 1], kv.y, a1);
                    a2 = fmaf(q[d + 2], kv.z, a2);
                    a3 = fmaf(q[d + 3], kv.w, a3);
                }
                int kpos = kt * 64 + j0 + jj;
                sc[jj] = (a0 + a1 + a2 + a3) * scale
                         - slope * fabsf((float)(q_idx - kpos));
            }
            float mt = m;
            #pragma unroll
            for (int jj = 0; jj < 8; jj++) mt = fmaxf(mt, sc[jj]);
            float corr = __expf(m - mt);
            m = mt;
            l *= corr;
            #pragma unroll
            for (int d = 0; d < HDIM; d++) o[d] *= corr;
            #pragma unroll
            for (int jj = 0; jj < 8; jj++) {
                float p = __expf(sc[jj] - m);
                l += p;
                const float* vr = &Vs[j0 + jj][0];
                #pragma unroll
                for (int d = 0; d < HDIM; d += 4) {
                    float4 vv = *(const float4*)(vr + d);
                    o[d + 0] = fmaf(p, vv.x, o[d + 0]);
                    o[d + 1] = fmaf(p, vv.y, o[d + 1]);
                    o[d + 2] = fmaf(p, vv.z, o[d + 2]);
                    o[d + 3] = fmaf(p, vv.w, o[d + 3]);
                }
            }
        }
    }

    float inv = 1.0f / l;
    float* orow = out + (size_t)(b * SEQ + q_idx) * DM + h * HDIM;
    #pragma unroll
    for (int d = 0; d < HDIM; d += 4) {
        float4 v;
        v.x = o[d] * inv; v.y = o[d + 1] * inv;
        v.z = o[d + 2] * inv; v.w = o[d + 3] * inv;
        *(float4*)(orow + d) = v;
    }
}

// ---------------- silu(gate) * up (in place into gate) ----------------------
__global__ void silu_mul_kernel(const float4* __restrict__ g,
                                const float4* __restrict__ u,
                                float4* __restrict__ o, int n4)
{
    int i = blockIdx.x * blockDim.x + threadIdx.x;
    if (i >= n4) return;
    float4 gv = g[i], uv = u[i], r;
    r.x = uv.x * gv.x / (1.0f + __expf(-gv.x));
    r.y = uv.y * gv.y / (1.0f + __expf(-gv.y));
    r.z = uv.z * gv.z / (1.0f + __expf(-gv.z));
    r.w = uv.w * gv.w / (1.0f + __expf(-gv.w));
    o[i] = r;
}

// ---------------- host orchestration ----------------------------------------
extern "C" void kernel_launch(void* const* d_in, const int* in_sizes, int n_in,
                              void* d_out, int out_size)
{
    const float* cls_tokens = (const float*)d_in[0];
    const float* cls_token  = (const float*)d_in[1];
    const float* log_slopes = (const float*)d_in[2];
    const float* Wqkv       = (const float*)d_in[3];
    const float* Wo         = (const float*)d_in[4];
    const float* Wg         = (const float*)d_in[5];
    const float* Wu         = (const float*)d_in[6];
    const float* Wd         = (const float*)d_in[7];
    const float* ln1w       = (const float*)d_in[8];
    const float* ln1b       = (const float*)d_in[9];
    const float* ln2w       = (const float*)d_in[10];
    const float* ln2b       = (const float*)d_in[11];
    const float* finw       = (const float*)d_in[12];
    const float* finb       = (const float*)d_in[13];
    float* out = (float*)d_out;

    float *x, *h, *qkv, *attn, *gate, *up;
    cudaGetSymbolAddress((void**)&x,    g_x);
    cudaGetSymbolAddress((void**)&h,    g_h);
    cudaGetSymbolAddress((void**)&qkv,  g_qkv);
    cudaGetSymbolAddress((void**)&attn, g_attn);
    cudaGetSymbolAddress((void**)&gate, g_gate);
    cudaGetSymbolAddress((void**)&up,   g_up);

    build_x_kernel<<<(MTOK * DM + 255) / 256, 256>>>(cls_tokens, cls_token, x);

    for (int l = 0; l < LAYERS; l++) {
        const float* wqkv = Wqkv + (size_t)l * 3 * DM * DM;
        const float* wo   = Wo   + (size_t)l * DM * DM;
        const float* wg   = Wg   + (size_t)l * FFDIM * DM;
        const float* wu   = Wu   + (size_t)l * FFDIM * DM;
        const float* wd   = Wd   + (size_t)l * DM * FFDIM;

        layernorm_kernel<<<MTOK, 256>>>(x, DM, h, ln1w + l * DM, ln1b + l * DM);

        sgemm_nt_kernel<0><<<dim3(3 * DM / 128, MTOK / 128), 256>>>(
            h, wqkv, nullptr, qkv, MTOK, 3 * DM, DM);

        flash_attn_kernel<<<dim3(SEQ / 128, NH, BATCH), 128>>>(qkv, log_slopes, attn);

        sgemm_nt_kernel<1><<<dim3(DM / 128, MTOK / 128), 256>>>(
            attn, wo, x, x, MTOK, DM, DM);

        layernorm_kernel<<<MTOK, 256>>>(x, DM, h, ln2w + l * DM, ln2b + l * DM);

        sgemm_nt_kernel<0><<<dim3(FFDIM / 128, MTOK / 128), 256>>>(
            h, wg, nullptr, gate, MTOK, FFDIM, DM);
        sgemm_nt_kernel<0><<<dim3(FFDIM / 128, MTOK / 128), 256>>>(
            h, wu, nullptr, up, MTOK, FFDIM, DM);

        int n4 = MTOK * FFDIM / 4;
        silu_mul_kernel<<<(n4 + 255) / 256, 256>>>(
            (const float4*)gate, (const float4*)up, (float4*)gate, n4);

        sgemm_nt_kernel<1><<<dim3(DM / 128, MTOK / 128), 256>>>(
            gate, wd, x, x, MTOK, DM, FFDIM);
    }

    // final LN over x[:,0,:] (row stride SEQ*DM picks the CLS row per batch)
    layernorm_kernel<<<BATCH, 256>>>(x, (size_t)SEQ * DM, out, finw, finb);
}

// round 4
// speedup vs baseline: 1.0726x; 1.0726x over previous
#include <cuda_runtime.h>
#include <math.h>

// ---------------- problem constants ----------------
#define LAYERS 6
#define BATCH  4
#define SEQ    1024
#define DM     768
#define NH     16
#define HDIM   48
#define FFDIM  3072
#define MTOK   (BATCH*SEQ)   // 4096

typedef unsigned long long u64;

// ---------------- f32x2 packed helpers (sm_103a FFMA2 path) -----------------
__device__ __forceinline__ void ffma2(u64 &d, u64 a, u64 b) {
    asm("fma.rn.f32x2 %0, %1, %2, %0;" : "+l"(d) : "l"(a), "l"(b));
}
__device__ __forceinline__ u64 fmul2(u64 a, u64 b) {
    u64 r; asm("mul.rn.f32x2 %0, %1, %2;" : "=l"(r) : "l"(a), "l"(b)); return r;
}
__device__ __forceinline__ u64 fadd2(u64 a, u64 b) {
    u64 r; asm("add.rn.f32x2 %0, %1, %2;" : "=l"(r) : "l"(a), "l"(b)); return r;
}
__device__ __forceinline__ u64 pack2(float x) {
    u64 r; asm("mov.b64 %0, {%1, %1};" : "=l"(r) : "f"(x)); return r;
}
__device__ __forceinline__ float2 unpack2(u64 v) {
    float2 f; asm("mov.b64 {%0, %1}, %2;" : "=f"(f.x), "=f"(f.y) : "l"(v)); return f;
}

// ---------------- scratch (device globals; no allocation allowed) ----------
__device__ float g_x   [MTOK*DM];
__device__ float g_h   [MTOK*DM];
__device__ float g_qkv [MTOK*3*DM];
__device__ float g_attn[MTOK*DM];
__device__ float g_gate[MTOK*FFDIM];
__device__ float g_up  [MTOK*FFDIM];

// ---------------- build x = concat(cls_token, cls_tokens) -------------------
__global__ void build_x_kernel(const float* __restrict__ cls_tokens,
                               const float* __restrict__ cls_token,
                               float* __restrict__ x)
{
    int idx = blockIdx.x * blockDim.x + threadIdx.x;
    if (idx >= MTOK * DM) return;
    int row = idx / DM;
    int d   = idx - row * DM;
    int b   = row >> 10;
    int s   = row & (SEQ - 1);
    float v;
    if (s == 0) v = cls_token[d];
    else        v = cls_tokens[((b * (SEQ - 1)) + (s - 1)) * DM + d];
    x[idx] = v;
}

// ---------------- layernorm over rows of 768 --------------------------------
__global__ __launch_bounds__(256) void layernorm_kernel(
    const float* __restrict__ in, size_t in_stride,
    float* __restrict__ out,
    const float* __restrict__ w, const float* __restrict__ b)
{
    int row = blockIdx.x;
    const float* xr = in + (size_t)row * in_stride;
    int t = threadIdx.x;

    float v0 = xr[t], v1 = xr[t + 256], v2 = xr[t + 512];
    float s  = v0 + v1 + v2;
    float sq = v0 * v0 + v1 * v1 + v2 * v2;
    #pragma unroll
    for (int o = 16; o > 0; o >>= 1) {
        s  += __shfl_xor_sync(0xFFFFFFFFu, s,  o);
        sq += __shfl_xor_sync(0xFFFFFFFFu, sq, o);
    }
    __shared__ float ss[8], sqs[8];
    int wid = t >> 5, lane = t & 31;
    if (lane == 0) { ss[wid] = s; sqs[wid] = sq; }
    __syncthreads();
    float ts = 0.f, tq = 0.f;
    #pragma unroll
    for (int i = 0; i < 8; i++) { ts += ss[i]; tq += sqs[i]; }
    float mean = ts * (1.0f / DM);
    float var  = tq * (1.0f / DM) - mean * mean;
    float rstd = rsqrtf(var + 1e-5f);

    float* orow = out + (size_t)row * DM;
    orow[t]       = (v0 - mean) * rstd * w[t]       + b[t];
    orow[t + 256] = (v1 - mean) * rstd * w[t + 256] + b[t + 256];
    orow[t + 512] = (v2 - mean) * rstd * w[t + 512] + b[t + 512];
}

// ---------------- SGEMM (f32x2 packed): C[M,N] = (Cin +) A @ B^T ------------
// 128x128x16 tile, 256 threads, 8x8 micro-tile held as 8 rows x 4 f32x2 pairs.
template <int EPI_ADD>
__global__ __launch_bounds__(256) void sgemm_nt_kernel(
    const float* __restrict__ A, const float* __restrict__ B,
    const float* __restrict__ Cin, float* __restrict__ C,
    int M, int N, int K)
{
    const int BM = 128, BN = 128, BK = 16;
    __shared__ __align__(16) float As[BK][BM];
    __shared__ __align__(16) float Bs[BK][BN];

    int bm = blockIdx.y * BM;
    int bn = blockIdx.x * BN;
    int tid = threadIdx.x;
    int tr = (tid >> 4) * 8;
    int tc = (tid & 15) * 8;

    u64 acc2[8][4];
    #pragma unroll
    for (int i = 0; i < 8; i++)
        #pragma unroll
        for (int j = 0; j < 4; j++) acc2[i][j] = 0ull;

    for (int k0 = 0; k0 < K; k0 += BK) {
        #pragma unroll
        for (int i = 0; i < 2; i++) {
            int idx = tid * 2 + i;
            int r = idx >> 2;
            int c = (idx & 3) * 4;
            float4 v = *(const float4*)&A[(size_t)(bm + r) * K + k0 + c];
            As[c + 0][r] = v.x; As[c + 1][r] = v.y;
            As[c + 2][r] = v.z; As[c + 3][r] = v.w;
        }
        #pragma unroll
        for (int i = 0; i < 2; i++) {
            int idx = tid * 2 + i;
            int r = idx >> 2;
            int c = (idx & 3) * 4;
            float4 v = *(const float4*)&B[(size_t)(bn + r) * K + k0 + c];
            Bs[c + 0][r] = v.x; Bs[c + 1][r] = v.y;
            Bs[c + 2][r] = v.z; Bs[c + 3][r] = v.w;
        }
        __syncthreads();

        #pragma unroll
        for (int k = 0; k < BK; k++) {
            float a[8];
            *(float4*)&a[0] = *(const float4*)&As[k][tr];
            *(float4*)&a[4] = *(const float4*)&As[k][tr + 4];
            double2 blo = *(const double2*)&Bs[k][tc];
            double2 bhi = *(const double2*)&Bs[k][tc + 4];
            u64 b2[4];
            b2[0] = __double_as_longlong(blo.x);
            b2[1] = __double_as_longlong(blo.y);
            b2[2] = __double_as_longlong(bhi.x);
            b2[3] = __double_as_longlong(bhi.y);
            #pragma unroll
            for (int i = 0; i < 8; i++) {
                u64 ad = pack2(a[i]);
                ffma2(acc2[i][0], ad, b2[0]);
                ffma2(acc2[i][1], ad, b2[1]);
                ffma2(acc2[i][2], ad, b2[2]);
                ffma2(acc2[i][3], ad, b2[3]);
            }
        }
        __syncthreads();
    }

    #pragma unroll
    for (int i = 0; i < 8; i++) {
        size_t row = (size_t)(bm + tr + i) * N + bn + tc;
        #pragma unroll
        for (int j = 0; j < 4; j += 2) {
            u64 r0 = acc2[i][j], r1 = acc2[i][j + 1];
            if (EPI_ADD) {
                double2 cv = *(const double2*)&Cin[row + 2 * j];
                r0 = fadd2(r0, __double_as_longlong(cv.x));
                r1 = fadd2(r1, __double_as_longlong(cv.y));
            }
            double2 ov;
            ov.x = __longlong_as_double(r0);
            ov.y = __longlong_as_double(r1);
            *(double2*)&C[row + 2 * j] = ov;
        }
    }
}

// ---------------- flash attention with ALiBi (f32x2 packed) ------------------
__global__ __launch_bounds__(128) void flash_attn_kernel(
    const float* __restrict__ qkv, const float* __restrict__ log_slopes,
    float* __restrict__ out)
{
    const int QW = 3 * DM;  // 2304
    const int HD2 = HDIM / 2;  // 24 packed pairs
    int qt = blockIdx.x, h = blockIdx.y, b = blockIdx.z;
    int t  = threadIdx.x;
    int q_idx = qt * 128 + t;

    float slope = __expf(log_slopes[h]);
    const float scale = 0.14433756729740643f;  // 1/sqrt(48)

    const float* qrow = qkv + (size_t)(b * SEQ + q_idx) * QW + h * HDIM;
    u64 q2[HD2];
    #pragma unroll
    for (int d = 0; d < HD2; d += 2) {
        double2 v = *(const double2*)(qrow + 2 * d);
        q2[d]     = __double_as_longlong(v.x);
        q2[d + 1] = __double_as_longlong(v.y);
    }

    u64 o2[HD2];
    #pragma unroll
    for (int d = 0; d < HD2; d++) o2[d] = 0ull;
    float m = -INFINITY, l = 0.f;

    __shared__ __align__(16) float Ks[64][HDIM];
    __shared__ __align__(16) float Vs[64][HDIM];

    for (int kt = 0; kt < SEQ / 64; kt++) {
        __syncthreads();
        #pragma unroll
        for (int i = 0; i < 6; i++) {
            int idx = t * 6 + i;
            int r = idx / 12;
            int c = (idx % 12) * 4;
            const float* krow = qkv + (size_t)(b * SEQ + kt * 64 + r) * QW
                                + DM + h * HDIM + c;
            *(float4*)&Ks[r][c] = *(const float4*)krow;
            *(float4*)&Vs[r][c] = *(const float4*)(krow + DM);
        }
        __syncthreads();

        #pragma unroll 1
        for (int j0 = 0; j0 < 64; j0 += 8) {
            float sc[8];
            #pragma unroll
            for (int jj = 0; jj < 8; jj++) {
                const float* kr = &Ks[j0 + jj][0];
                u64 acc0 = 0ull, acc1 = 0ull;
                #pragma unroll
                for (int d = 0; d < HD2; d += 2) {
                    double2 kv = *(const double2*)(kr + 2 * d);
                    ffma2(acc0, q2[d],     __double_as_longlong(kv.x));
                    ffma2(acc1, q2[d + 1], __double_as_longlong(kv.y));
                }
                float2 s0 = unpack2(acc0);
                float2 s1 = unpack2(acc1);
                int kpos = kt * 64 + j0 + jj;
                sc[jj] = (s0.x + s0.y + s1.x + s1.y) * scale
                         - slope * fabsf((float)(q_idx - kpos));
            }
            float mt = m;
            #pragma unroll
            for (int jj = 0; jj < 8; jj++) mt = fmaxf(mt, sc[jj]);
            float corr = __expf(m - mt);
            m = mt;
            l *= corr;
            u64 corr2 = pack2(corr);
            #pragma unroll
            for (int d = 0; d < HD2; d++) o2[d] = fmul2(o2[d], corr2);
            #pragma unroll
            for (int jj = 0; jj < 8; jj++) {
                float p = __expf(sc[jj] - m);
                l += p;
                u64 p2 = pack2(p);
                const float* vr = &Vs[j0 + jj][0];
                #pragma unroll
                for (int d = 0; d < HD2; d += 2) {
                    double2 vv = *(const double2*)(vr + 2 * d);
                    ffma2(o2[d],     p2, __double_as_longlong(vv.x));
                    ffma2(o2[d + 1], p2, __double_as_longlong(vv.y));
                }
            }
        }
    }

    float inv = 1.0f / l;
    u64 inv2 = pack2(inv);
    float* orow = out + (size_t)(b * SEQ + q_idx) * DM + h * HDIM;
    #pragma unroll
    for (int d = 0; d < HD2; d += 2) {
        double2 ov;
        ov.x = __longlong_as_double(fmul2(o2[d],     inv2));
        ov.y = __longlong_as_double(fmul2(o2[d + 1], inv2));
        *(double2*)(orow + 2 * d) = ov;
    }
}

// ---------------- silu(gate) * up (in place into gate) ----------------------
__global__ void silu_mul_kernel(const float4* __restrict__ g,
                                const float4* __restrict__ u,
                                float4* __restrict__ o, int n4)
{
    int i = blockIdx.x * blockDim.x + threadIdx.x;
    if (i >= n4) return;
    float4 gv = g[i], uv = u[i], r;
    r.x = uv.x * gv.x / (1.0f + __expf(-gv.x));
    r.y = uv.y * gv.y / (1.0f + __expf(-gv.y));
    r.z = uv.z * gv.z / (1.0f + __expf(-gv.z));
    r.w = uv.w * gv.w / (1.0f + __expf(-gv.w));
    o[i] = r;
}

// ---------------- host orchestration ----------------------------------------
extern "C" void kernel_launch(void* const* d_in, const int* in_sizes, int n_in,
                              void* d_out, int out_size)
{
    const float* cls_tokens = (const float*)d_in[0];
    const float* cls_token  = (const float*)d_in[1];
    const float* log_slopes = (const float*)d_in[2];
    const float* Wqkv       = (const float*)d_in[3];
    const float* Wo         = (const float*)d_in[4];
    const float* Wg         = (const float*)d_in[5];
    const float* Wu         = (const float*)d_in[6];
    const float* Wd         = (const float*)d_in[7];
    const float* ln1w       = (const float*)d_in[8];
    const float* ln1b       = (const float*)d_in[9];
    const float* ln2w       = (const float*)d_in[10];
    const float* ln2b       = (const float*)d_in[11];
    const float* finw       = (const float*)d_in[12];
    const float* finb       = (const float*)d_in[13];
    float* out = (float*)d_out;

    float *x, *h, *qkv, *attn, *gate, *up;
    cudaGetSymbolAddress((void**)&x,    g_x);
    cudaGetSymbolAddress((void**)&h,    g_h);
    cudaGetSymbolAddress((void**)&qkv,  g_qkv);
    cudaGetSymbolAddress((void**)&attn, g_attn);
    cudaGetSymbolAddress((void**)&gate, g_gate);
    cudaGetSymbolAddress((void**)&up,   g_up);

    build_x_kernel<<<(MTOK * DM + 255) / 256, 256>>>(cls_tokens, cls_token, x);

    for (int l = 0; l < LAYERS; l++) {
        const float* wqkv = Wqkv + (size_t)l * 3 * DM * DM;
        const float* wo   = Wo   + (size_t)l * DM * DM;
        const float* wg   = Wg   + (size_t)l * FFDIM * DM;
        const float* wu   = Wu   + (size_t)l * FFDIM * DM;
        const float* wd   = Wd   + (size_t)l * DM * FFDIM;

        layernorm_kernel<<<MTOK, 256>>>(x, DM, h, ln1w + l * DM, ln1b + l * DM);

        sgemm_nt_kernel<0><<<dim3(3 * DM / 128, MTOK / 128), 256>>>(
            h, wqkv, nullptr, qkv, MTOK, 3 * DM, DM);

        flash_attn_kernel<<<dim3(SEQ / 128, NH, BATCH), 128>>>(qkv, log_slopes, attn);

        sgemm_nt_kernel<1><<<dim3(DM / 128, MTOK / 128), 256>>>(
            attn, wo, x, x, MTOK, DM, DM);

        layernorm_kernel<<<MTOK, 256>>>(x, DM, h, ln2w + l * DM, ln2b + l * DM);

        sgemm_nt_kernel<0><<<dim3(FFDIM / 128, MTOK / 128), 256>>>(
            h, wg, nullptr, gate, MTOK, FFDIM, DM);
        sgemm_nt_kernel<0><<<dim3(FFDIM / 128, MTOK / 128), 256>>>(
            h, wu, nullptr, up, MTOK, FFDIM, DM);

        int n4 = MTOK * FFDIM / 4;
        silu_mul_kernel<<<(n4 + 255) / 256, 256>>>(
            (const float4*)gate, (const float4*)up, (float4*)gate, n4);

        sgemm_nt_kernel<1><<<dim3(DM / 128, MTOK / 128), 256>>>(
            gate, wd, x, x, MTOK, DM, FFDIM);
    }

    layernorm_kernel<<<BATCH, 256>>>(x, (size_t)SEQ * DM, out, finw, finb);
}

// round 7
// speedup vs baseline: 1.5163x; 1.4137x over previous
#include <cuda_runtime.h>
#include <cuda_bf16.h>
#include <math.h>
#include <stdint.h>

// ---------------- problem constants ----------------
#define LAYERS 6
#define BATCH  4
#define SEQ    1024
#define DM     768
#define NH     16
#define HDIM   48
#define FFDIM  3072
#define MTOK   (BATCH*SEQ)   // 4096

typedef unsigned long long u64;
typedef __nv_bfloat16  bf16;
typedef __nv_bfloat162 bf162;

// ---------------- f32x2 packed helpers (attention) --------------------------
__device__ __forceinline__ void ffma2(u64 &d, u64 a, u64 b) {
    asm("fma.rn.f32x2 %0, %1, %2, %0;" : "+l"(d) : "l"(a), "l"(b));
}
__device__ __forceinline__ u64 fmul2(u64 a, u64 b) {
    u64 r; asm("mul.rn.f32x2 %0, %1, %2;" : "=l"(r) : "l"(a), "l"(b)); return r;
}
__device__ __forceinline__ u64 pack2(float x) {
    u64 r; asm("mov.b64 %0, {%1, %1};" : "=l"(r) : "f"(x)); return r;
}
__device__ __forceinline__ float2 unpack2(u64 v) {
    float2 f; asm("mov.b64 {%0, %1}, %2;" : "=f"(f.x), "=f"(f.y) : "l"(v)); return f;
}

// ---------------- mma.sync / ldmatrix / cp.async helpers (plain sm_80+) -----
__device__ __forceinline__ uint32_t smem_u32(const void* p) {
    uint32_t a;
    asm("{ .reg .u64 t; cvta.to.shared.u64 t, %1; cvt.u32.u64 %0, t; }"
        : "=r"(a) : "l"(p));
    return a;
}
__device__ __forceinline__ void cp16(uint32_t dst, const void* src) {
    asm volatile("cp.async.cg.shared.global [%0], [%1], 16;" :: "r"(dst), "l"(src));
}
#define CP_COMMIT() asm volatile("cp.async.commit_group;" ::: "memory")
#define CP_WAIT1()  asm volatile("cp.async.wait_group 1;" ::: "memory")
#define CP_WAIT0()  asm volatile("cp.async.wait_group 0;" ::: "memory")

__device__ __forceinline__ void ldsm4(uint32_t &r0, uint32_t &r1,
                                      uint32_t &r2, uint32_t &r3, uint32_t addr) {
    asm volatile("ldmatrix.sync.aligned.m8n8.x4.shared.b16 {%0,%1,%2,%3}, [%4];"
                 : "=r"(r0), "=r"(r1), "=r"(r2), "=r"(r3) : "r"(addr));
}
__device__ __forceinline__ void mma16816(float* d, const uint32_t* a,
                                         const uint32_t* b) {
    asm volatile("mma.sync.aligned.m16n8k16.row.col.f32.bf16.bf16.f32 "
        "{%0,%1,%2,%3}, {%4,%5,%6,%7}, {%8,%9}, {%0,%1,%2,%3};"
        : "+f"(d[0]), "+f"(d[1]), "+f"(d[2]), "+f"(d[3])
        : "r"(a[0]), "r"(a[1]), "r"(a[2]), "r"(a[3]), "r"(b[0]), "r"(b[1]));
}

// ---------------- scratch (device globals) ----------------------------------
__device__ __align__(16) float g_x   [MTOK*DM];
__device__ __align__(16) float g_qkv [MTOK*3*DM];
__device__ __align__(16) float g_gate[MTOK*FFDIM];
__device__ __align__(16) float g_up  [MTOK*FFDIM];

__device__ __align__(16) bf16 g_h_hi [MTOK*DM];
__device__ __align__(16) bf16 g_h_lo [MTOK*DM];
__device__ __align__(16) bf16 g_at_hi[MTOK*DM];
__device__ __align__(16) bf16 g_at_lo[MTOK*DM];
__device__ __align__(16) bf16 g_g_hi [MTOK*FFDIM];
__device__ __align__(16) bf16 g_g_lo [MTOK*FFDIM];

__device__ __align__(16) bf16 g_wqkv_hi[LAYERS*3*DM*DM];
__device__ __align__(16) bf16 g_wqkv_lo[LAYERS*3*DM*DM];
__device__ __align__(16) bf16 g_wo_hi  [LAYERS*DM*DM];
__device__ __align__(16) bf16 g_wo_lo  [LAYERS*DM*DM];
__device__ __align__(16) bf16 g_wg_hi  [LAYERS*FFDIM*DM];
__device__ __align__(16) bf16 g_wg_lo  [LAYERS*FFDIM*DM];
__device__ __align__(16) bf16 g_wu_hi  [LAYERS*FFDIM*DM];
__device__ __align__(16) bf16 g_wu_lo  [LAYERS*FFDIM*DM];
__device__ __align__(16) bf16 g_wd_hi  [LAYERS*DM*FFDIM];
__device__ __align__(16) bf16 g_wd_lo  [LAYERS*DM*FFDIM];

// ---------------- split helpers ---------------------------------------------
__device__ __forceinline__ void split1(float x, bf16 &h, bf16 &l) {
    h = __float2bfloat16(x);
    l = __float2bfloat16(x - __bfloat162float(h));
}

__global__ void split4_kernel(const float4* __restrict__ in,
                              bf162* __restrict__ hi, bf162* __restrict__ lo,
                              int n4)
{
    int i = blockIdx.x * blockDim.x + threadIdx.x;
    if (i >= n4) return;
    float4 v = in[i];
    bf16 h0, l0, h1, l1, h2, l2, h3, l3;
    split1(v.x, h0, l0); split1(v.y, h1, l1);
    split1(v.z, h2, l2); split1(v.w, h3, l3);
    bf162 H0; H0.x = h0; H0.y = h1;
    bf162 H1; H1.x = h2; H1.y = h3;
    bf162 L0; L0.x = l0; L0.y = l1;
    bf162 L1; L1.x = l2; L1.y = l3;
    hi[i * 2] = H0; hi[i * 2 + 1] = H1;
    lo[i * 2] = L0; lo[i * 2 + 1] = L1;
}

// ---------------- build x ----------------------------------------------------
__global__ void build_x_kernel(const float* __restrict__ cls_tokens,
                               const float* __restrict__ cls_token,
                               float* __restrict__ x)
{
    int idx = blockIdx.x * blockDim.x + threadIdx.x;
    if (idx >= MTOK * DM) return;
    int row = idx / DM;
    int d   = idx - row * DM;
    int b   = row >> 10;
    int s   = row & (SEQ - 1);
    float v;
    if (s == 0) v = cls_token[d];
    else        v = cls_tokens[((b * (SEQ - 1)) + (s - 1)) * DM + d];
    x[idx] = v;
}

// ---------------- layernorm (fp32 out) ---------------------------------------
__global__ __launch_bounds__(256) void layernorm_kernel(
    const float* __restrict__ in, size_t in_stride, float* __restrict__ out,
    const float* __restrict__ w, const float* __restrict__ b)
{
    int row = blockIdx.x;
    const float* xr = in + (size_t)row * in_stride;
    int t = threadIdx.x;
    float v0 = xr[t], v1 = xr[t + 256], v2 = xr[t + 512];
    float s  = v0 + v1 + v2;
    float sq = v0 * v0 + v1 * v1 + v2 * v2;
    #pragma unroll
    for (int o = 16; o > 0; o >>= 1) {
        s  += __shfl_xor_sync(0xFFFFFFFFu, s,  o);
        sq += __shfl_xor_sync(0xFFFFFFFFu, sq, o);
    }
    __shared__ float ss[8], sqs[8];
    int wid = t >> 5, lane = t & 31;
    if (lane == 0) { ss[wid] = s; sqs[wid] = sq; }
    __syncthreads();
    float ts = 0.f, tq = 0.f;
    #pragma unroll
    for (int i = 0; i < 8; i++) { ts += ss[i]; tq += sqs[i]; }
    float mean = ts * (1.0f / DM);
    float var  = tq * (1.0f / DM) - mean * mean;
    float rstd = rsqrtf(var + 1e-5f);
    float* orow = out + (size_t)row * DM;
    orow[t]       = (v0 - mean) * rstd * w[t]       + b[t];
    orow[t + 256] = (v1 - mean) * rstd * w[t + 256] + b[t + 256];
    orow[t + 512] = (v2 - mean) * rstd * w[t + 512] + b[t + 512];
}

// ---------------- layernorm with fused bf16 hi/lo split ----------------------
__global__ __launch_bounds__(256) void layernorm_split_kernel(
    const float* __restrict__ in, bf16* __restrict__ ohi, bf16* __restrict__ olo,
    const float* __restrict__ w, const float* __restrict__ b)
{
    int row = blockIdx.x;
    const float* xr = in + (size_t)row * DM;
    int t = threadIdx.x;
    float v0 = xr[t], v1 = xr[t + 256], v2 = xr[t + 512];
    float s  = v0 + v1 + v2;
    float sq = v0 * v0 + v1 * v1 + v2 * v2;
    #pragma unroll
    for (int o = 16; o > 0; o >>= 1) {
        s  += __shfl_xor_sync(0xFFFFFFFFu, s,  o);
        sq += __shfl_xor_sync(0xFFFFFFFFu, sq, o);
    }
    __shared__ float ss[8], sqs[8];
    int wid = t >> 5, lane = t & 31;
    if (lane == 0) { ss[wid] = s; sqs[wid] = sq; }
    __syncthreads();
    float ts = 0.f, tq = 0.f;
    #pragma unroll
    for (int i = 0; i < 8; i++) { ts += ss[i]; tq += sqs[i]; }
    float mean = ts * (1.0f / DM);
    float var  = tq * (1.0f / DM) - mean * mean;
    float rstd = rsqrtf(var + 1e-5f);
    size_t base = (size_t)row * DM;
    #pragma unroll
    for (int j = 0; j < 3; j++) {
        float v = (j == 0 ? v0 : (j == 1 ? v1 : v2));
        float y = (v - mean) * rstd * w[t + j * 256] + b[t + j * 256];
        bf16 h, l; split1(y, h, l);
        ohi[base + t + j * 256] = h;
        olo[base + t + j * 256] = l;
    }
}

// ---------------- HMMA bf16 split GEMM ---------------------------------------
// C[M,N] = (Cin +) (Ah+Al)[M,K] @ (Bh+Bl)[N,K]^T  (drops Al*Bl)
// 128x128x32 CTA tile, 256 threads (8 warps of 64x32), cp.async double buffer,
// ldmatrix + mma.sync.m16n8k16 (plain sm_80-feature path -> compiles on sm_103).
template <int EPI_ADD>
__global__ __launch_bounds__(256) void mma_gemm_kernel(
    const bf16* __restrict__ Ah, const bf16* __restrict__ Al,
    const bf16* __restrict__ Bh, const bf16* __restrict__ Bl,
    const float* __restrict__ Cin, float* __restrict__ C,
    int M, int N, int K)
{
    __shared__ __align__(16) bf16 As[2][128 * 32];
    __shared__ __align__(16) bf16 Bs[2][128 * 32];

    int tid = threadIdx.x, wid = tid >> 5, lane = tid & 31;
    int bm = blockIdx.y * 128, bn = blockIdx.x * 128;
    int wm = (wid & 1) * 64;     // warp row  (2 warps along M)
    int wn = (wid >> 1) * 32;    // warp col  (4 warps along N)

    uint32_t sA = smem_u32(As), sB = smem_u32(Bs);

    float acc[4][4][4];
    #pragma unroll
    for (int i = 0; i < 4; i++)
        #pragma unroll
        for (int j = 0; j < 4; j++)
            #pragma unroll
            for (int q = 0; q < 4; q++) acc[i][j][q] = 0.f;

    const int ktiles = K >> 5;
    const int T = 3 * ktiles;

    // chunk copy geometry: idx 0..511 -> row = idx>>2 (128), c = idx&3 (16B units)
    int r0c = (tid * 2) >> 2;
    int c0c = (tid * 2) & 3;
    int r1c = (tid * 2 + 1) >> 2;
    int c1c = (tid * 2 + 1) & 3;
    uint32_t swA0 = (uint32_t)(r0c * 64 + ((c0c ^ (r0c & 3)) << 4));
    uint32_t swA1 = (uint32_t)(r1c * 64 + ((c1c ^ (r1c & 3)) << 4));

    auto issue = [&](int t) {
        int pass = t / ktiles;
        int k0 = (t - pass * ktiles) << 5;
        const bf16* Ap = (pass == 2) ? Al : Ah;
        const bf16* Bp = (pass == 1) ? Bl : Bh;
        uint32_t aB = sA + (uint32_t)((t & 1) * 8192);
        uint32_t bB = sB + (uint32_t)((t & 1) * 8192);
        cp16(aB + swA0, Ap + (size_t)(bm + r0c) * K + k0 + c0c * 8);
        cp16(aB + swA1, Ap + (size_t)(bm + r1c) * K + k0 + c1c * 8);
        cp16(bB + swA0, Bp + (size_t)(bn + r0c) * K + k0 + c0c * 8);
        cp16(bB + swA1, Bp + (size_t)(bn + r1c) * K + k0 + c1c * 8);
        CP_COMMIT();
    };

    issue(0);
    for (int t = 0; t < T; t++) {
        if (t + 1 < T) { issue(t + 1); CP_WAIT1(); }
        else          { CP_WAIT0(); }
        __syncthreads();

        uint32_t aB = sA + (uint32_t)((t & 1) * 8192);
        uint32_t bB = sB + (uint32_t)((t & 1) * 8192);

        #pragma unroll
        for (int ks = 0; ks < 2; ks++) {
            uint32_t a[4][4];
            #pragma unroll
            for (int mt = 0; mt < 4; mt++) {
                int row = wm + mt * 16 + (lane & 15);
                int c = (ks * 16 + ((lane >> 4) << 3)) >> 3;
                uint32_t addr = aB + row * 64 + ((c ^ (row & 3)) << 4);
                ldsm4(a[mt][0], a[mt][1], a[mt][2], a[mt][3], addr);
            }
            uint32_t b[4][2];
            #pragma unroll
            for (int p = 0; p < 2; p++) {
                int n = wn + p * 16 + (lane & 7) + ((lane >> 4) << 3);
                int c = (ks * 16 + (((lane >> 3) & 1) << 3)) >> 3;
                uint32_t addr = bB + n * 64 + ((c ^ (n & 3)) << 4);
                ldsm4(b[2 * p][0], b[2 * p][1], b[2 * p + 1][0], b[2 * p + 1][1], addr);
            }
            #pragma unroll
            for (int mt = 0; mt < 4; mt++)
                #pragma unroll
                for (int nt = 0; nt < 4; nt++)
                    mma16816(acc[mt][nt], a[mt], b[nt]);
        }
        __syncthreads();
    }

    // epilogue
    int grp = lane >> 2, tig = lane & 3;
    #pragma unroll
    for (int mt = 0; mt < 4; mt++) {
        #pragma unroll
        for (int nt = 0; nt < 4; nt++) {
            int row = bm + wm + mt * 16 + grp;
            int col = bn + wn + nt * 8 + tig * 2;
            float2 v0, v1;
            v0.x = acc[mt][nt][0]; v0.y = acc[mt][nt][1];
            v1.x = acc[mt][nt][2]; v1.y = acc[mt][nt][3];
            size_t o0 = (size_t)row * N + col;
            size_t o1 = (size_t)(row + 8) * N + col;
            if (EPI_ADD) {
                float2 c0 = *(const float2*)&Cin[o0];
                float2 c1 = *(const float2*)&Cin[o1];
                v0.x += c0.x; v0.y += c0.y;
                v1.x += c1.x; v1.y += c1.y;
            }
            *(float2*)&C[o0] = v0;
            *(float2*)&C[o1] = v1;
        }
    }
}

// ---------------- flash attention with ALiBi (f32x2), bf16-split output ------
__global__ __launch_bounds__(128) void flash_attn_kernel(
    const float* __restrict__ qkv, const float* __restrict__ log_slopes,
    bf16* __restrict__ out_hi, bf16* __restrict__ out_lo)
{
    const int QW = 3 * DM;
    const int HD2 = HDIM / 2;
    int qt = blockIdx.x, h = blockIdx.y, b = blockIdx.z;
    int t  = threadIdx.x;
    int q_idx = qt * 128 + t;

    float slope = __expf(log_slopes[h]);
    const float scale = 0.14433756729740643f;

    const float* qrow = qkv + (size_t)(b * SEQ + q_idx) * QW + h * HDIM;
    u64 q2[HD2];
    #pragma unroll
    for (int d = 0; d < HD2; d += 2) {
        double2 v = *(const double2*)(qrow + 2 * d);
        q2[d]     = __double_as_longlong(v.x);
        q2[d + 1] = __double_as_longlong(v.y);
    }

    u64 o2[HD2];
    #pragma unroll
    for (int d = 0; d < HD2; d++) o2[d] = 0ull;
    float m = -INFINITY, l = 0.f;

    __shared__ __align__(16) float Ks[64][HDIM];
    __shared__ __align__(16) float Vs[64][HDIM];

    for (int kt = 0; kt < SEQ / 64; kt++) {
        __syncthreads();
        #pragma unroll
        for (int i = 0; i < 6; i++) {
            int idx = t * 6 + i;
            int r = idx / 12;
            int c = (idx % 12) * 4;
            const float* krow = qkv + (size_t)(b * SEQ + kt * 64 + r) * QW
                                + DM + h * HDIM + c;
            *(float4*)&Ks[r][c] = *(const float4*)krow;
            *(float4*)&Vs[r][c] = *(const float4*)(krow + DM);
        }
        __syncthreads();

        #pragma unroll 1
        for (int j0 = 0; j0 < 64; j0 += 8) {
            float sc[8];
            #pragma unroll
            for (int jj = 0; jj < 8; jj++) {
                const float* kr = &Ks[j0 + jj][0];
                u64 acc0 = 0ull, acc1 = 0ull;
                #pragma unroll
                for (int d = 0; d < HD2; d += 2) {
                    double2 kv = *(const double2*)(kr + 2 * d);
                    ffma2(acc0, q2[d],     __double_as_longlong(kv.x));
                    ffma2(acc1, q2[d + 1], __double_as_longlong(kv.y));
                }
                float2 s0 = unpack2(acc0);
                float2 s1 = unpack2(acc1);
                int kpos = kt * 64 + j0 + jj;
                sc[jj] = (s0.x + s0.y + s1.x + s1.y) * scale
                         - slope * fabsf((float)(q_idx - kpos));
            }
            float mt = m;
            #pragma unroll
            for (int jj = 0; jj < 8; jj++) mt = fmaxf(mt, sc[jj]);
            float corr = __expf(m - mt);
            m = mt;
            l *= corr;
            u64 corr2 = pack2(corr);
            #pragma unroll
            for (int d = 0; d < HD2; d++) o2[d] = fmul2(o2[d], corr2);
            #pragma unroll
            for (int jj = 0; jj < 8; jj++) {
                float p = __expf(sc[jj] - m);
                l += p;
                u64 p2 = pack2(p);
                const float* vr = &Vs[j0 + jj][0];
                #pragma unroll
                for (int d = 0; d < HD2; d += 2) {
                    double2 vv = *(const double2*)(vr + 2 * d);
                    ffma2(o2[d],     p2, __double_as_longlong(vv.x));
                    ffma2(o2[d + 1], p2, __double_as_longlong(vv.y));
                }
            }
        }
    }

    float inv = 1.0f / l;
    size_t obase = (size_t)(b * SEQ + q_idx) * DM + h * HDIM;
    #pragma unroll
    for (int d = 0; d < HD2; d++) {
        float2 v = unpack2(o2[d]);
        float y0 = v.x * inv, y1 = v.y * inv;
        bf16 h0, l0, h1, l1;
        split1(y0, h0, l0); split1(y1, h1, l1);
        bf162 H; H.x = h0; H.y = h1;
        bf162 L; L.x = l0; L.y = l1;
        *(bf162*)(out_hi + obase + 2 * d) = H;
        *(bf162*)(out_lo + obase + 2 * d) = L;
    }
}

// ---------------- silu(gate)*up with fused bf16 split ------------------------
__global__ void silu_split_kernel(const float4* __restrict__ g,
                                  const float4* __restrict__ u,
                                  bf162* __restrict__ ohi, bf162* __restrict__ olo,
                                  int n4)
{
    int i = blockIdx.x * blockDim.x + threadIdx.x;
    if (i >= n4) return;
    float4 gv = g[i], uv = u[i];
    float y0 = uv.x * gv.x / (1.0f + __expf(-gv.x));
    float y1 = uv.y * gv.y / (1.0f + __expf(-gv.y));
    float y2 = uv.z * gv.z / (1.0f + __expf(-gv.z));
    float y3 = uv.w * gv.w / (1.0f + __expf(-gv.w));
    bf16 h0, l0, h1, l1, h2, l2, h3, l3;
    split1(y0, h0, l0); split1(y1, h1, l1);
    split1(y2, h2, l2); split1(y3, h3, l3);
    bf162 H0; H0.x = h0; H0.y = h1;
    bf162 H1; H1.x = h2; H1.y = h3;
    bf162 L0; L0.x = l0; L0.y = l1;
    bf162 L1; L1.x = l2; L1.y = l3;
    ohi[i * 2] = H0; ohi[i * 2 + 1] = H1;
    olo[i * 2] = L0; olo[i * 2 + 1] = L1;
}

// ---------------- host orchestration ----------------------------------------
static void run_gemm(int epi, const bf16* ah, const bf16* al,
                     const bf16* bh, const bf16* bl,
                     const float* cin, float* c, int M, int N, int K)
{
    dim3 grid(N / 128, M / 128);
    if (epi)
        mma_gemm_kernel<1><<<grid, 256>>>(ah, al, bh, bl, cin, c, M, N, K);
    else
        mma_gemm_kernel<0><<<grid, 256>>>(ah, al, bh, bl, cin, c, M, N, K);
}

extern "C" void kernel_launch(void* const* d_in, const int* in_sizes, int n_in,
                              void* d_out, int out_size)
{
    const float* cls_tokens = (const float*)d_in[0];
    const float* cls_token  = (const float*)d_in[1];
    const float* log_slopes = (const float*)d_in[2];
    const float* Wqkv       = (const float*)d_in[3];
    const float* Wo         = (const float*)d_in[4];
    const float* Wg         = (const float*)d_in[5];
    const float* Wu         = (const float*)d_in[6];
    const float* Wd         = (const float*)d_in[7];
    const float* ln1w       = (const float*)d_in[8];
    const float* ln1b       = (const float*)d_in[9];
    const float* ln2w       = (const float*)d_in[10];
    const float* ln2b       = (const float*)d_in[11];
    const float* finw       = (const float*)d_in[12];
    const float* finb       = (const float*)d_in[13];
    float* out = (float*)d_out;

    float *x, *qkv, *gate, *up;
    bf16 *h_hi, *h_lo, *at_hi, *at_lo, *gg_hi, *gg_lo;
    bf16 *wqkv_hi, *wqkv_lo, *wo_hi, *wo_lo, *wg_hi, *wg_lo,
         *wu_hi, *wu_lo, *wd_hi, *wd_lo;
    cudaGetSymbolAddress((void**)&x,    g_x);
    cudaGetSymbolAddress((void**)&qkv,  g_qkv);
    cudaGetSymbolAddress((void**)&gate, g_gate);
    cudaGetSymbolAddress((void**)&up,   g_up);
    cudaGetSymbolAddress((void**)&h_hi, g_h_hi);
    cudaGetSymbolAddress((void**)&h_lo, g_h_lo);
    cudaGetSymbolAddress((void**)&at_hi, g_at_hi);
    cudaGetSymbolAddress((void**)&at_lo, g_at_lo);
    cudaGetSymbolAddress((void**)&gg_hi, g_g_hi);
    cudaGetSymbolAddress((void**)&gg_lo, g_g_lo);
    cudaGetSymbolAddress((void**)&wqkv_hi, g_wqkv_hi);
    cudaGetSymbolAddress((void**)&wqkv_lo, g_wqkv_lo);
    cudaGetSymbolAddress((void**)&wo_hi, g_wo_hi);
    cudaGetSymbolAddress((void**)&wo_lo, g_wo_lo);
    cudaGetSymbolAddress((void**)&wg_hi, g_wg_hi);
    cudaGetSymbolAddress((void**)&wg_lo, g_wg_lo);
    cudaGetSymbolAddress((void**)&wu_hi, g_wu_hi);
    cudaGetSymbolAddress((void**)&wu_lo, g_wu_lo);
    cudaGetSymbolAddress((void**)&wd_hi, g_wd_hi);
    cudaGetSymbolAddress((void**)&wd_lo, g_wd_lo);

    // weight conversion (fp32 -> bf16 hi/lo), once per launch
    {
        int n;
        n = LAYERS * 3 * DM * DM / 4;
        split4_kernel<<<(n + 255) / 256, 256>>>((const float4*)Wqkv,
            (bf162*)wqkv_hi, (bf162*)wqkv_lo, n);
        n = LAYERS * DM * DM / 4;
        split4_kernel<<<(n + 255) / 256, 256>>>((const float4*)Wo,
            (bf162*)wo_hi, (bf162*)wo_lo, n);
        n = LAYERS * FFDIM * DM / 4;
        split4_kernel<<<(n + 255) / 256, 256>>>((const float4*)Wg,
            (bf162*)wg_hi, (bf162*)wg_lo, n);
        split4_kernel<<<(n + 255) / 256, 256>>>((const float4*)Wu,
            (bf162*)wu_hi, (bf162*)wu_lo, n);
        n = LAYERS * DM * FFDIM / 4;
        split4_kernel<<<(n + 255) / 256, 256>>>((const float4*)Wd,
            (bf162*)wd_hi, (bf162*)wd_lo, n);
    }

    build_x_kernel<<<(MTOK * DM + 255) / 256, 256>>>(cls_tokens, cls_token, x);

    for (int l = 0; l < LAYERS; l++) {
        size_t oq = (size_t)l * 3 * DM * DM;
        size_t oo = (size_t)l * DM * DM;
        size_t og = (size_t)l * FFDIM * DM;
        size_t od = (size_t)l * DM * FFDIM;

        layernorm_split_kernel<<<MTOK, 256>>>(x, h_hi, h_lo,
                                              ln1w + l * DM, ln1b + l * DM);

        run_gemm(0, h_hi, h_lo, wqkv_hi + oq, wqkv_lo + oq,
                 nullptr, qkv, MTOK, 3 * DM, DM);

        flash_attn_kernel<<<dim3(SEQ / 128, NH, BATCH), 128>>>(
            qkv, log_slopes, at_hi, at_lo);

        run_gemm(1, at_hi, at_lo, wo_hi + oo, wo_lo + oo,
                 x, x, MTOK, DM, DM);

        layernorm_split_kernel<<<MTOK, 256>>>(x, h_hi, h_lo,
                                              ln2w + l * DM, ln2b + l * DM);

        run_gemm(0, h_hi, h_lo, wg_hi + og, wg_lo + og,
                 nullptr, gate, MTOK, FFDIM, DM);
        run_gemm(0, h_hi, h_lo, wu_hi + og, wu_lo + og,
                 nullptr, up, MTOK, FFDIM, DM);

        int n4 = MTOK * FFDIM / 4;
        silu_split_kernel<<<(n4 + 255) / 256, 256>>>(
            (const float4*)gate, (const float4*)up,
            (bf162*)gg_hi, (bf162*)gg_lo, n4);

        run_gemm(1, gg_hi, gg_lo, wd_hi + od, wd_lo + od,
                 x, x, MTOK, DM, FFDIM);
    }

    layernorm_kernel<<<BATCH, 256>>>(x, (size_t)SEQ * DM, out, finw, finb);
}

// round 9
// speedup vs baseline: 2.0140x; 1.3282x over previous
#include <cuda_runtime.h>
#include <cuda_bf16.h>
#include <math.h>
#include <stdint.h>

// ---------------- problem constants ----------------
#define LAYERS 6
#define BATCH  4
#define SEQ    1024
#define DM     768
#define NH     16
#define HDIM   48
#define FFDIM  3072
#define MTOK   (BATCH*SEQ)   // 4096

typedef unsigned long long u64;
typedef __nv_bfloat16  bf16;
typedef __nv_bfloat162 bf162;

// ---------------- f32x2 packed helpers (attention) --------------------------
__device__ __forceinline__ void ffma2(u64 &d, u64 a, u64 b) {
    asm("fma.rn.f32x2 %0, %1, %2, %0;" : "+l"(d) : "l"(a), "l"(b));
}
__device__ __forceinline__ u64 fmul2(u64 a, u64 b) {
    u64 r; asm("mul.rn.f32x2 %0, %1, %2;" : "=l"(r) : "l"(a), "l"(b)); return r;
}
__device__ __forceinline__ u64 pack2(float x) {
    u64 r; asm("mov.b64 %0, {%1, %1};" : "=l"(r) : "f"(x)); return r;
}
__device__ __forceinline__ float2 unpack2(u64 v) {
    float2 f; asm("mov.b64 {%0, %1}, %2;" : "=f"(f.x), "=f"(f.y) : "l"(v)); return f;
}

// ---------------- mma.sync / ldmatrix / cp.async helpers --------------------
__device__ __forceinline__ uint32_t smem_u32(const void* p) {
    uint32_t a;
    asm("{ .reg .u64 t; cvta.to.shared.u64 t, %1; cvt.u32.u64 %0, t; }"
        : "=r"(a) : "l"(p));
    return a;
}
__device__ __forceinline__ void cp16(uint32_t dst, const void* src) {
    asm volatile("cp.async.cg.shared.global [%0], [%1], 16;" :: "r"(dst), "l"(src));
}
#define CP_COMMIT() asm volatile("cp.async.commit_group;" ::: "memory")
#define CP_WAIT1()  asm volatile("cp.async.wait_group 1;" ::: "memory")
#define CP_WAIT0()  asm volatile("cp.async.wait_group 0;" ::: "memory")

__device__ __forceinline__ void ldsm4(uint32_t &r0, uint32_t &r1,
                                      uint32_t &r2, uint32_t &r3, uint32_t addr) {
    asm volatile("ldmatrix.sync.aligned.m8n8.x4.shared.b16 {%0,%1,%2,%3}, [%4];"
                 : "=r"(r0), "=r"(r1), "=r"(r2), "=r"(r3) : "r"(addr));
}
__device__ __forceinline__ void mma16816(float* d, const uint32_t* a,
                                         const uint32_t* b) {
    asm volatile("mma.sync.aligned.m16n8k16.row.col.f32.bf16.bf16.f32 "
        "{%0,%1,%2,%3}, {%4,%5,%6,%7}, {%8,%9}, {%0,%1,%2,%3};"
        : "+f"(d[0]), "+f"(d[1]), "+f"(d[2]), "+f"(d[3])
        : "r"(a[0]), "r"(a[1]), "r"(a[2]), "r"(a[3]), "r"(b[0]), "r"(b[1]));
}

// ---------------- scratch (device globals) ----------------------------------
__device__ __align__(16) float g_x   [MTOK*DM];
__device__ __align__(16) float g_qkv [MTOK*3*DM];
__device__ __align__(16) float g_gate[MTOK*FFDIM];
__device__ __align__(16) float g_up  [MTOK*FFDIM];

__device__ __align__(16) bf16 g_h_hi [MTOK*DM];
__device__ __align__(16) bf16 g_h_lo [MTOK*DM];
__device__ __align__(16) bf16 g_at_hi[MTOK*DM];
__device__ __align__(16) bf16 g_at_lo[MTOK*DM];
__device__ __align__(16) bf16 g_g_hi [MTOK*FFDIM];
__device__ __align__(16) bf16 g_g_lo [MTOK*FFDIM];

__device__ __align__(16) bf16 g_wqkv_hi[LAYERS*3*DM*DM];
__device__ __align__(16) bf16 g_wqkv_lo[LAYERS*3*DM*DM];
__device__ __align__(16) bf16 g_wo_hi  [LAYERS*DM*DM];
__device__ __align__(16) bf16 g_wo_lo  [LAYERS*DM*DM];
__device__ __align__(16) bf16 g_wg_hi  [LAYERS*FFDIM*DM];
__device__ __align__(16) bf16 g_wg_lo  [LAYERS*FFDIM*DM];
__device__ __align__(16) bf16 g_wu_hi  [LAYERS*FFDIM*DM];
__device__ __align__(16) bf16 g_wu_lo  [LAYERS*FFDIM*DM];
__device__ __align__(16) bf16 g_wd_hi  [LAYERS*DM*FFDIM];
__device__ __align__(16) bf16 g_wd_lo  [LAYERS*DM*FFDIM];

// ---------------- split helpers ---------------------------------------------
__device__ __forceinline__ void split1(float x, bf16 &h, bf16 &l) {
    h = __float2bfloat16(x);
    l = __float2bfloat16(x - __bfloat162float(h));
}

__global__ void split4_kernel(const float4* __restrict__ in,
                              bf162* __restrict__ hi, bf162* __restrict__ lo,
                              int n4)
{
    int i = blockIdx.x * blockDim.x + threadIdx.x;
    if (i >= n4) return;
    float4 v = in[i];
    bf16 h0, l0, h1, l1, h2, l2, h3, l3;
    split1(v.x, h0, l0); split1(v.y, h1, l1);
    split1(v.z, h2, l2); split1(v.w, h3, l3);
    bf162 H0; H0.x = h0; H0.y = h1;
    bf162 H1; H1.x = h2; H1.y = h3;
    bf162 L0; L0.x = l0; L0.y = l1;
    bf162 L1; L1.x = l2; L1.y = l3;
    hi[i * 2] = H0; hi[i * 2 + 1] = H1;
    lo[i * 2] = L0; lo[i * 2 + 1] = L1;
}

// ---------------- build x ----------------------------------------------------
__global__ void build_x_kernel(const float* __restrict__ cls_tokens,
                               const float* __restrict__ cls_token,
                               float* __restrict__ x)
{
    int idx = blockIdx.x * blockDim.x + threadIdx.x;
    if (idx >= MTOK * DM) return;
    int row = idx / DM;
    int d   = idx - row * DM;
    int b   = row >> 10;
    int s   = row & (SEQ - 1);
    float v;
    if (s == 0) v = cls_token[d];
    else        v = cls_tokens[((b * (SEQ - 1)) + (s - 1)) * DM + d];
    x[idx] = v;
}

// ---------------- layernorm (fp32 out) ---------------------------------------
__global__ __launch_bounds__(256) void layernorm_kernel(
    const float* __restrict__ in, size_t in_stride, float* __restrict__ out,
    const float* __restrict__ w, const float* __restrict__ b)
{
    int row = blockIdx.x;
    const float* xr = in + (size_t)row * in_stride;
    int t = threadIdx.x;
    float v0 = xr[t], v1 = xr[t + 256], v2 = xr[t + 512];
    float s  = v0 + v1 + v2;
    float sq = v0 * v0 + v1 * v1 + v2 * v2;
    #pragma unroll
    for (int o = 16; o > 0; o >>= 1) {
        s  += __shfl_xor_sync(0xFFFFFFFFu, s,  o);
        sq += __shfl_xor_sync(0xFFFFFFFFu, sq, o);
    }
    __shared__ float ss[8], sqs[8];
    int wid = t >> 5, lane = t & 31;
    if (lane == 0) { ss[wid] = s; sqs[wid] = sq; }
    __syncthreads();
    float ts = 0.f, tq = 0.f;
    #pragma unroll
    for (int i = 0; i < 8; i++) { ts += ss[i]; tq += sqs[i]; }
    float mean = ts * (1.0f / DM);
    float var  = tq * (1.0f / DM) - mean * mean;
    float rstd = rsqrtf(var + 1e-5f);
    float* orow = out + (size_t)row * DM;
    orow[t]       = (v0 - mean) * rstd * w[t]       + b[t];
    orow[t + 256] = (v1 - mean) * rstd * w[t + 256] + b[t + 256];
    orow[t + 512] = (v2 - mean) * rstd * w[t + 512] + b[t + 512];
}

// ---------------- layernorm with fused bf16 hi/lo split ----------------------
__global__ __launch_bounds__(256) void layernorm_split_kernel(
    const float* __restrict__ in, bf16* __restrict__ ohi, bf16* __restrict__ olo,
    const float* __restrict__ w, const float* __restrict__ b)
{
    int row = blockIdx.x;
    const float* xr = in + (size_t)row * DM;
    int t = threadIdx.x;
    float v0 = xr[t], v1 = xr[t + 256], v2 = xr[t + 512];
    float s  = v0 + v1 + v2;
    float sq = v0 * v0 + v1 * v1 + v2 * v2;
    #pragma unroll
    for (int o = 16; o > 0; o >>= 1) {
        s  += __shfl_xor_sync(0xFFFFFFFFu, s,  o);
        sq += __shfl_xor_sync(0xFFFFFFFFu, sq, o);
    }
    __shared__ float ss[8], sqs[8];
    int wid = t >> 5, lane = t & 31;
    if (lane == 0) { ss[wid] = s; sqs[wid] = sq; }
    __syncthreads();
    float ts = 0.f, tq = 0.f;
    #pragma unroll
    for (int i = 0; i < 8; i++) { ts += ss[i]; tq += sqs[i]; }
    float mean = ts * (1.0f / DM);
    float var  = tq * (1.0f / DM) - mean * mean;
    float rstd = rsqrtf(var + 1e-5f);
    size_t base = (size_t)row * DM;
    #pragma unroll
    for (int j = 0; j < 3; j++) {
        float v = (j == 0 ? v0 : (j == 1 ? v1 : v2));
        float y = (v - mean) * rstd * w[t + j * 256] + b[t + j * 256];
        bf16 h, l; split1(y, h, l);
        ohi[base + t + j * 256] = h;
        olo[base + t + j * 256] = l;
    }
}

// ---------------- fused 3-term HMMA bf16 split GEMM --------------------------
// C[M,N] = (Cin +) Ah@Bh^T + Ah@Bl^T + Al@Bh^T
// 128x128x32 CTA tile, 256 threads (8 warps, 64x32 warp tile).
// Per k-stage all four tiles (Ah,Al,Bh,Bl) are staged; all 3 MMA combos run
// in one mainloop -> 3x fewer stages/syncs than the 3-pass version.
// Dynamic smem: 2 stages * 4 tiles * 8KB = 64KB.
#define GSTAGE 32768
template <int EPI_ADD>
__global__ __launch_bounds__(256) void mma_gemm_kernel(
    const bf16* __restrict__ Ah, const bf16* __restrict__ Al,
    const bf16* __restrict__ Bh, const bf16* __restrict__ Bl,
    const float* __restrict__ Cin, float* __restrict__ C,
    int M, int N, int K)
{
    extern __shared__ __align__(16) char dynsmem[];
    uint32_t sS = smem_u32(dynsmem);

    int tid = threadIdx.x, wid = tid >> 5, lane = tid & 31;
    int bm = blockIdx.y * 128, bn = blockIdx.x * 128;
    int wm = (wid & 1) * 64;
    int wn = (wid >> 1) * 32;

    float acc[4][4][4];
    #pragma unroll
    for (int i = 0; i < 4; i++)
        #pragma unroll
        for (int j = 0; j < 4; j++)
            #pragma unroll
            for (int q = 0; q < 4; q++) acc[i][j][q] = 0.f;

    const int T = K >> 5;

    // copy geometry: 512 16B-chunks per tile, 2 per thread
    int r0c = (tid * 2) >> 2;
    int c0c = (tid * 2) & 3;
    int r1c = (tid * 2 + 1) >> 2;
    int c1c = (tid * 2 + 1) & 3;
    uint32_t swA0 = (uint32_t)(r0c * 64 + ((c0c ^ (r0c & 3)) << 4));
    uint32_t swA1 = (uint32_t)(r1c * 64 + ((c1c ^ (r1c & 3)) << 4));

    auto issue = [&](int t) {
        int k0 = t << 5;
        uint32_t st = sS + (uint32_t)((t & 1) * GSTAGE);
        size_t a0 = (size_t)(bm + r0c) * K + k0;
        size_t a1 = (size_t)(bm + r1c) * K + k0;
        size_t b0 = (size_t)(bn + r0c) * K + k0;
        size_t b1 = (size_t)(bn + r1c) * K + k0;
        cp16(st + 0     + swA0, Ah + a0 + c0c * 8);
        cp16(st + 0     + swA1, Ah + a1 + c1c * 8);
        cp16(st + 8192  + swA0, Al + a0 + c0c * 8);
        cp16(st + 8192  + swA1, Al + a1 + c1c * 8);
        cp16(st + 16384 + swA0, Bh + b0 + c0c * 8);
        cp16(st + 16384 + swA1, Bh + b1 + c1c * 8);
        cp16(st + 24576 + swA0, Bl + b0 + c0c * 8);
        cp16(st + 24576 + swA1, Bl + b1 + c1c * 8);
        CP_COMMIT();
    };

    issue(0);
    for (int t = 0; t < T; t++) {
        if (t + 1 < T) { issue(t + 1); CP_WAIT1(); }
        else          { CP_WAIT0(); }
        __syncthreads();

        uint32_t st = sS + (uint32_t)((t & 1) * GSTAGE);

        #pragma unroll
        for (int ks = 0; ks < 2; ks++) {
            uint32_t aH[4][4], aL[4][4];
            #pragma unroll
            for (int mt = 0; mt < 4; mt++) {
                int row = wm + mt * 16 + (lane & 15);
                int c = (ks * 16 + ((lane >> 4) << 3)) >> 3;
                uint32_t off = (uint32_t)(row * 64 + ((c ^ (row & 3)) << 4));
                ldsm4(aH[mt][0], aH[mt][1], aH[mt][2], aH[mt][3], st + off);
                ldsm4(aL[mt][0], aL[mt][1], aL[mt][2], aL[mt][3], st + 8192 + off);
            }
            uint32_t bH[4][2], bL[4][2];
            #pragma unroll
            for (int p = 0; p < 2; p++) {
                int n = wn + p * 16 + (lane & 7) + ((lane >> 4) << 3);
                int c = (ks * 16 + (((lane >> 3) & 1) << 3)) >> 3;
                uint32_t off = (uint32_t)(n * 64 + ((c ^ (n & 3)) << 4));
                ldsm4(bH[2 * p][0], bH[2 * p][1], bH[2 * p + 1][0], bH[2 * p + 1][1],
                      st + 16384 + off);
                ldsm4(bL[2 * p][0], bL[2 * p][1], bL[2 * p + 1][0], bL[2 * p + 1][1],
                      st + 24576 + off);
            }
            #pragma unroll
            for (int mt = 0; mt < 4; mt++)
                #pragma unroll
                for (int nt = 0; nt < 4; nt++) {
                    mma16816(acc[mt][nt], aH[mt], bH[nt]);
                    mma16816(acc[mt][nt], aH[mt], bL[nt]);
                    mma16816(acc[mt][nt], aL[mt], bH[nt]);
                }
        }
        __syncthreads();
    }

    int grp = lane >> 2, tig = lane & 3;
    #pragma unroll
    for (int mt = 0; mt < 4; mt++) {
        #pragma unroll
        for (int nt = 0; nt < 4; nt++) {
            int row = bm + wm + mt * 16 + grp;
            int col = bn + wn + nt * 8 + tig * 2;
            float2 v0, v1;
            v0.x = acc[mt][nt][0]; v0.y = acc[mt][nt][1];
            v1.x = acc[mt][nt][2]; v1.y = acc[mt][nt][3];
            size_t o0 = (size_t)row * N + col;
            size_t o1 = (size_t)(row + 8) * N + col;
            if (EPI_ADD) {
                float2 c0 = *(const float2*)&Cin[o0];
                float2 c1 = *(const float2*)&Cin[o1];
                v0.x += c0.x; v0.y += c0.y;
                v1.x += c1.x; v1.y += c1.y;
            }
            *(float2*)&C[o0] = v0;
            *(float2*)&C[o1] = v1;
        }
    }
}
#define GEMM_SMEM (2 * GSTAGE)

// ---------------- flash attention with ALiBi (f32x2), bf16-split output ------
__global__ __launch_bounds__(128) void flash_attn_kernel(
    const float* __restrict__ qkv, const float* __restrict__ log_slopes,
    bf16* __restrict__ out_hi, bf16* __restrict__ out_lo)
{
    const int QW = 3 * DM;
    const int HD2 = HDIM / 2;
    int qt = blockIdx.x, h = blockIdx.y, b = blockIdx.z;
    int t  = threadIdx.x;
    int q_idx = qt * 128 + t;

    float slope = __expf(log_slopes[h]);
    const float scale = 0.14433756729740643f;

    const float* qrow = qkv + (size_t)(b * SEQ + q_idx) * QW + h * HDIM;
    u64 q2[HD2];
    #pragma unroll
    for (int d = 0; d < HD2; d += 2) {
        double2 v = *(const double2*)(qrow + 2 * d);
        q2[d]     = __double_as_longlong(v.x);
        q2[d + 1] = __double_as_longlong(v.y);
    }

    u64 o2[HD2];
    #pragma unroll
    for (int d = 0; d < HD2; d++) o2[d] = 0ull;
    float m = -INFINITY, l = 0.f;

    __shared__ __align__(16) float Ks[64][HDIM];
    __shared__ __align__(16) float Vs[64][HDIM];

    for (int kt = 0; kt < SEQ / 64; kt++) {
        __syncthreads();
        #pragma unroll
        for (int i = 0; i < 6; i++) {
            int idx = t * 6 + i;
            int r = idx / 12;
            int c = (idx % 12) * 4;
            const float* krow = qkv + (size_t)(b * SEQ + kt * 64 + r) * QW
                                + DM + h * HDIM + c;
            *(float4*)&Ks[r][c] = *(const float4*)krow;
            *(float4*)&Vs[r][c] = *(const float4*)(krow + DM);
        }
        __syncthreads();

        #pragma unroll 1
        for (int j0 = 0; j0 < 64; j0 += 8) {
            float sc[8];
            #pragma unroll
            for (int jj = 0; jj < 8; jj++) {
                const float* kr = &Ks[j0 + jj][0];
                u64 acc0 = 0ull, acc1 = 0ull;
                #pragma unroll
                for (int d = 0; d < HD2; d += 2) {
                    double2 kv = *(const double2*)(kr + 2 * d);
                    ffma2(acc0, q2[d],     __double_as_longlong(kv.x));
                    ffma2(acc1, q2[d + 1], __double_as_longlong(kv.y));
                }
                float2 s0 = unpack2(acc0);
                float2 s1 = unpack2(acc1);
                int kpos = kt * 64 + j0 + jj;
                sc[jj] = (s0.x + s0.y + s1.x + s1.y) * scale
                         - slope * fabsf((float)(q_idx - kpos));
            }
            float mt = m;
            #pragma unroll
            for (int jj = 0; jj < 8; jj++) mt = fmaxf(mt, sc[jj]);
            float corr = __expf(m - mt);
            m = mt;
            l *= corr;
            u64 corr2 = pack2(corr);
            #pragma unroll
            for (int d = 0; d < HD2; d++) o2[d] = fmul2(o2[d], corr2);
            #pragma unroll
            for (int jj = 0; jj < 8; jj++) {
                float p = __expf(sc[jj] - m);
                l += p;
                u64 p2 = pack2(p);
                const float* vr = &Vs[j0 + jj][0];
                #pragma unroll
                for (int d = 0; d < HD2; d += 2) {
                    double2 vv = *(const double2*)(vr + 2 * d);
                    ffma2(o2[d],     p2, __double_as_longlong(vv.x));
                    ffma2(o2[d + 1], p2, __double_as_longlong(vv.y));
                }
            }
        }
    }

    float inv = 1.0f / l;
    size_t obase = (size_t)(b * SEQ + q_idx) * DM + h * HDIM;
    #pragma unroll
    for (int d = 0; d < HD2; d++) {
        float2 v = unpack2(o2[d]);
        float y0 = v.x * inv, y1 = v.y * inv;
        bf16 h0, l0, h1, l1;
        split1(y0, h0, l0); split1(y1, h1, l1);
        bf162 H; H.x = h0; H.y = h1;
        bf162 L; L.x = l0; L.y = l1;
        *(bf162*)(out_hi + obase + 2 * d) = H;
        *(bf162*)(out_lo + obase + 2 * d) = L;
    }
}

// ---------------- silu(gate)*up with fused bf16 split ------------------------
__global__ void silu_split_kernel(const float4* __restrict__ g,
                                  const float4* __restrict__ u,
                                  bf162* __restrict__ ohi, bf162* __restrict__ olo,
                                  int n4)
{
    int i = blockIdx.x * blockDim.x + threadIdx.x;
    if (i >= n4) return;
    float4 gv = g[i], uv = u[i];
    float y0 = uv.x * gv.x / (1.0f + __expf(-gv.x));
    float y1 = uv.y * gv.y / (1.0f + __expf(-gv.y));
    float y2 = uv.z * gv.z / (1.0f + __expf(-gv.z));
    float y3 = uv.w * gv.w / (1.0f + __expf(-gv.w));
    bf16 h0, l0, h1, l1, h2, l2, h3, l3;
    split1(y0, h0, l0); split1(y1, h1, l1);
    split1(y2, h2, l2); split1(y3, h3, l3);
    bf162 H0; H0.x = h0; H0.y = h1;
    bf162 H1; H1.x = h2; H1.y = h3;
    bf162 L0; L0.x = l0; L0.y = l1;
    bf162 L1; L1.x = l2; L1.y = l3;
    ohi[i * 2] = H0; ohi[i * 2 + 1] = H1;
    olo[i * 2] = L0; olo[i * 2 + 1] = L1;
}

// ---------------- host orchestration ----------------------------------------
static void run_gemm(int epi, const bf16* ah, const bf16* al,
                     const bf16* bh, const bf16* bl,
                     const float* cin, float* c, int M, int N, int K)
{
    dim3 grid(N / 128, M / 128);
    if (epi)
        mma_gemm_kernel<1><<<grid, 256, GEMM_SMEM>>>(ah, al, bh, bl, cin, c, M, N, K);
    else
        mma_gemm_kernel<0><<<grid, 256, GEMM_SMEM>>>(ah, al, bh, bl, cin, c, M, N, K);
}

extern "C" void kernel_launch(void* const* d_in, const int* in_sizes, int n_in,
                              void* d_out, int out_size)
{
    const float* cls_tokens = (const float*)d_in[0];
    const float* cls_token  = (const float*)d_in[1];
    const float* log_slopes = (const float*)d_in[2];
    const float* Wqkv       = (const float*)d_in[3];
    const float* Wo         = (const float*)d_in[4];
    const float* Wg         = (const float*)d_in[5];
    const float* Wu         = (const float*)d_in[6];
    const float* Wd         = (const float*)d_in[7];
    const float* ln1w       = (const float*)d_in[8];
    const float* ln1b       = (const float*)d_in[9];
    const float* ln2w       = (const float*)d_in[10];
    const float* ln2b       = (const float*)d_in[11];
    const float* finw       = (const float*)d_in[12];
    const float* finb       = (const float*)d_in[13];
    float* out = (float*)d_out;

    cudaFuncSetAttribute(mma_gemm_kernel<0>,
                         cudaFuncAttributeMaxDynamicSharedMemorySize, GEMM_SMEM);
    cudaFuncSetAttribute(mma_gemm_kernel<1>,
                         cudaFuncAttributeMaxDynamicSharedMemorySize, GEMM_SMEM);

    float *x, *qkv, *gate, *up;
    bf16 *h_hi, *h_lo, *at_hi, *at_lo, *gg_hi, *gg_lo;
    bf16 *wqkv_hi, *wqkv_lo, *wo_hi, *wo_lo, *wg_hi, *wg_lo,
         *wu_hi, *wu_lo, *wd_hi, *wd_lo;
    cudaGetSymbolAddress((void**)&x,    g_x);
    cudaGetSymbolAddress((void**)&qkv,  g_qkv);
    cudaGetSymbolAddress((void**)&gate, g_gate);
    cudaGetSymbolAddress((void**)&up,   g_up);
    cudaGetSymbolAddress((void**)&h_hi, g_h_hi);
    cudaGetSymbolAddress((void**)&h_lo, g_h_lo);
    cudaGetSymbolAddress((void**)&at_hi, g_at_hi);
    cudaGetSymbolAddress((void**)&at_lo, g_at_lo);
    cudaGetSymbolAddress((void**)&gg_hi, g_g_hi);
    cudaGetSymbolAddress((void**)&gg_lo, g_g_lo);
    cudaGetSymbolAddress((void**)&wqkv_hi, g_wqkv_hi);
    cudaGetSymbolAddress((void**)&wqkv_lo, g_wqkv_lo);
    cudaGetSymbolAddress((void**)&wo_hi, g_wo_hi);
    cudaGetSymbolAddress((void**)&wo_lo, g_wo_lo);
    cudaGetSymbolAddress((void**)&wg_hi, g_wg_hi);
    cudaGetSymbolAddress((void**)&wg_lo, g_wg_lo);
    cudaGetSymbolAddress((void**)&wu_hi, g_wu_hi);
    cudaGetSymbolAddress((void**)&wu_lo, g_wu_lo);
    cudaGetSymbolAddress((void**)&wd_hi, g_wd_hi);
    cudaGetSymbolAddress((void**)&wd_lo, g_wd_lo);

    // weight conversion (fp32 -> bf16 hi/lo), once per launch
    {
        int n;
        n = LAYERS * 3 * DM * DM / 4;
        split4_kernel<<<(n + 255) / 256, 256>>>((const float4*)Wqkv,
            (bf162*)wqkv_hi, (bf162*)wqkv_lo, n);
        n = LAYERS * DM * DM / 4;
        split4_kernel<<<(n + 255) / 256, 256>>>((const float4*)Wo,
            (bf162*)wo_hi, (bf162*)wo_lo, n);
        n = LAYERS * FFDIM * DM / 4;
        split4_kernel<<<(n + 255) / 256, 256>>>((const float4*)Wg,
            (bf162*)wg_hi, (bf162*)wg_lo, n);
        split4_kernel<<<(n + 255) / 256, 256>>>((const float4*)Wu,
            (bf162*)wu_hi, (bf162*)wu_lo, n);
        n = LAYERS * DM * FFDIM / 4;
        split4_kernel<<<(n + 255) / 256, 256>>>((const float4*)Wd,
            (bf162*)wd_hi, (bf162*)wd_lo, n);
    }

    build_x_kernel<<<(MTOK * DM + 255) / 256, 256>>>(cls_tokens, cls_token, x);

    for (int l = 0; l < LAYERS; l++) {
        size_t oq = (size_t)l * 3 * DM * DM;
        size_t oo = (size_t)l * DM * DM;
        size_t og = (size_t)l * FFDIM * DM;
        size_t od = (size_t)l * DM * FFDIM;

        layernorm_split_kernel<<<MTOK, 256>>>(x, h_hi, h_lo,
                                              ln1w + l * DM, ln1b + l * DM);

        run_gemm(0, h_hi, h_lo, wqkv_hi + oq, wqkv_lo + oq,
                 nullptr, qkv, MTOK, 3 * DM, DM);

        flash_attn_kernel<<<dim3(SEQ / 128, NH, BATCH), 128>>>(
            qkv, log_slopes, at_hi, at_lo);

        run_gemm(1, at_hi, at_lo, wo_hi + oo, wo_lo + oo,
                 x, x, MTOK, DM, DM);

        layernorm_split_kernel<<<MTOK, 256>>>(x, h_hi, h_lo,
                                              ln2w + l * DM, ln2b + l * DM);

        run_gemm(0, h_hi, h_lo, wg_hi + og, wg_lo + og,
                 nullptr, gate, MTOK, FFDIM, DM);
        run_gemm(0, h_hi, h_lo, wu_hi + og, wu_lo + og,
                 nullptr, up, MTOK, FFDIM, DM);

        int n4 = MTOK * FFDIM / 4;
        silu_split_kernel<<<(n4 + 255) / 256, 256>>>(
            (const float4*)gate, (const float4*)up,
            (bf162*)gg_hi, (bf162*)gg_lo, n4);

        run_gemm(1, gg_hi, gg_lo, wd_hi + od, wd_lo + od,
                 x, x, MTOK, DM, FFDIM);
    }

    layernorm_kernel<<<BATCH, 256>>>(x, (size_t)SEQ * DM, out, finw, finb);
}

// round 10
// speedup vs baseline: 2.0666x; 1.0261x over previous
#include <cuda_runtime.h>
#include <cuda_bf16.h>
#include <math.h>
#include <stdint.h>

// ---------------- problem constants ----------------
#define LAYERS 6
#define BATCH  4
#define SEQ    1024
#define DM     768
#define NH     16
#define HDIM   48
#define FFDIM  3072
#define MTOK   (BATCH*SEQ)   // 4096
#define NSPLIT 4             // attention KV splits

typedef unsigned long long u64;
typedef __nv_bfloat16  bf16;
typedef __nv_bfloat162 bf162;

// ---------------- f32x2 packed helpers (attention) --------------------------
__device__ __forceinline__ void ffma2(u64 &d, u64 a, u64 b) {
    asm("fma.rn.f32x2 %0, %1, %2, %0;" : "+l"(d) : "l"(a), "l"(b));
}
__device__ __forceinline__ u64 fmul2(u64 a, u64 b) {
    u64 r; asm("mul.rn.f32x2 %0, %1, %2;" : "=l"(r) : "l"(a), "l"(b)); return r;
}
__device__ __forceinline__ u64 pack2(float x) {
    u64 r; asm("mov.b64 %0, {%1, %1};" : "=l"(r) : "f"(x)); return r;
}
__device__ __forceinline__ float2 unpack2(u64 v) {
    float2 f; asm("mov.b64 {%0, %1}, %2;" : "=f"(f.x), "=f"(f.y) : "l"(v)); return f;
}

// ---------------- mma.sync / ldmatrix / cp.async helpers --------------------
__device__ __forceinline__ uint32_t smem_u32(const void* p) {
    uint32_t a;
    asm("{ .reg .u64 t; cvta.to.shared.u64 t, %1; cvt.u32.u64 %0, t; }"
        : "=r"(a) : "l"(p));
    return a;
}
__device__ __forceinline__ void cp16(uint32_t dst, const void* src) {
    asm volatile("cp.async.cg.shared.global [%0], [%1], 16;" :: "r"(dst), "l"(src));
}
#define CP_COMMIT() asm volatile("cp.async.commit_group;" ::: "memory")
#define CP_WAIT2()  asm volatile("cp.async.wait_group 2;" ::: "memory")
#define CP_WAIT1()  asm volatile("cp.async.wait_group 1;" ::: "memory")
#define CP_WAIT0()  asm volatile("cp.async.wait_group 0;" ::: "memory")

__device__ __forceinline__ void ldsm4(uint32_t &r0, uint32_t &r1,
                                      uint32_t &r2, uint32_t &r3, uint32_t addr) {
    asm volatile("ldmatrix.sync.aligned.m8n8.x4.shared.b16 {%0,%1,%2,%3}, [%4];"
                 : "=r"(r0), "=r"(r1), "=r"(r2), "=r"(r3) : "r"(addr));
}
__device__ __forceinline__ void mma16816(float* d, const uint32_t* a,
                                         const uint32_t* b) {
    asm volatile("mma.sync.aligned.m16n8k16.row.col.f32.bf16.bf16.f32 "
        "{%0,%1,%2,%3}, {%4,%5,%6,%7}, {%8,%9}, {%0,%1,%2,%3};"
        : "+f"(d[0]), "+f"(d[1]), "+f"(d[2]), "+f"(d[3])
        : "r"(a[0]), "r"(a[1]), "r"(a[2]), "r"(a[3]), "r"(b[0]), "r"(b[1]));
}

// ---------------- scratch (device globals) ----------------------------------
__device__ __align__(16) float g_x   [MTOK*DM];
__device__ __align__(16) float g_qkv [MTOK*3*DM];
__device__ __align__(16) float g_gate[MTOK*FFDIM];
__device__ __align__(16) float g_up  [MTOK*FFDIM];

__device__ __align__(16) float g_opart [NSPLIT*MTOK*DM];   // unnormalized attn partials
__device__ __align__(16) float2 g_mlpart[NSPLIT*MTOK*NH];  // (m, l) per split/row/head

__device__ __align__(16) bf16 g_h_hi [MTOK*DM];
__device__ __align__(16) bf16 g_h_lo [MTOK*DM];
__device__ __align__(16) bf16 g_at_hi[MTOK*DM];
__device__ __align__(16) bf16 g_at_lo[MTOK*DM];
__device__ __align__(16) bf16 g_g_hi [MTOK*FFDIM];
__device__ __align__(16) bf16 g_g_lo [MTOK*FFDIM];

__device__ __align__(16) bf16 g_wqkv_hi[LAYERS*3*DM*DM];
__device__ __align__(16) bf16 g_wqkv_lo[LAYERS*3*DM*DM];
__device__ __align__(16) bf16 g_wo_hi  [LAYERS*DM*DM];
__device__ __align__(16) bf16 g_wo_lo  [LAYERS*DM*DM];
__device__ __align__(16) bf16 g_wg_hi  [LAYERS*FFDIM*DM];
__device__ __align__(16) bf16 g_wg_lo  [LAYERS*FFDIM*DM];
__device__ __align__(16) bf16 g_wu_hi  [LAYERS*FFDIM*DM];
__device__ __align__(16) bf16 g_wu_lo  [LAYERS*FFDIM*DM];
__device__ __align__(16) bf16 g_wd_hi  [LAYERS*DM*FFDIM];
__device__ __align__(16) bf16 g_wd_lo  [LAYERS*DM*FFDIM];

// ---------------- split helpers ---------------------------------------------
__device__ __forceinline__ void split1(float x, bf16 &h, bf16 &l) {
    h = __float2bfloat16(x);
    l = __float2bfloat16(x - __bfloat162float(h));
}

__global__ void split4_kernel(const float4* __restrict__ in,
                              bf162* __restrict__ hi, bf162* __restrict__ lo,
                              int n4)
{
    int i = blockIdx.x * blockDim.x + threadIdx.x;
    if (i >= n4) return;
    float4 v = in[i];
    bf16 h0, l0, h1, l1, h2, l2, h3, l3;
    split1(v.x, h0, l0); split1(v.y, h1, l1);
    split1(v.z, h2, l2); split1(v.w, h3, l3);
    bf162 H0; H0.x = h0; H0.y = h1;
    bf162 H1; H1.x = h2; H1.y = h3;
    bf162 L0; L0.x = l0; L0.y = l1;
    bf162 L1; L1.x = l2; L1.y = l3;
    hi[i * 2] = H0; hi[i * 2 + 1] = H1;
    lo[i * 2] = L0; lo[i * 2 + 1] = L1;
}

// ---------------- build x ----------------------------------------------------
__global__ void build_x_kernel(const float* __restrict__ cls_tokens,
                               const float* __restrict__ cls_token,
                               float* __restrict__ x)
{
    int idx = blockIdx.x * blockDim.x + threadIdx.x;
    if (idx >= MTOK * DM) return;
    int row = idx / DM;
    int d   = idx - row * DM;
    int b   = row >> 10;
    int s   = row & (SEQ - 1);
    float v;
    if (s == 0) v = cls_token[d];
    else        v = cls_tokens[((b * (SEQ - 1)) + (s - 1)) * DM + d];
    x[idx] = v;
}

// ---------------- layernorm (fp32 out) ---------------------------------------
__global__ __launch_bounds__(256) void layernorm_kernel(
    const float* __restrict__ in, size_t in_stride, float* __restrict__ out,
    const float* __restrict__ w, const float* __restrict__ b)
{
    int row = blockIdx.x;
    const float* xr = in + (size_t)row * in_stride;
    int t = threadIdx.x;
    float v0 = xr[t], v1 = xr[t + 256], v2 = xr[t + 512];
    float s  = v0 + v1 + v2;
    float sq = v0 * v0 + v1 * v1 + v2 * v2;
    #pragma unroll
    for (int o = 16; o > 0; o >>= 1) {
        s  += __shfl_xor_sync(0xFFFFFFFFu, s,  o);
        sq += __shfl_xor_sync(0xFFFFFFFFu, sq, o);
    }
    __shared__ float ss[8], sqs[8];
    int wid = t >> 5, lane = t & 31;
    if (lane == 0) { ss[wid] = s; sqs[wid] = sq; }
    __syncthreads();
    float ts = 0.f, tq = 0.f;
    #pragma unroll
    for (int i = 0; i < 8; i++) { ts += ss[i]; tq += sqs[i]; }
    float mean = ts * (1.0f / DM);
    float var  = tq * (1.0f / DM) - mean * mean;
    float rstd = rsqrtf(var + 1e-5f);
    float* orow = out + (size_t)row * DM;
    orow[t]       = (v0 - mean) * rstd * w[t]       + b[t];
    orow[t + 256] = (v1 - mean) * rstd * w[t + 256] + b[t + 256];
    orow[t + 512] = (v2 - mean) * rstd * w[t + 512] + b[t + 512];
}

// ---------------- layernorm with fused bf16 hi/lo split ----------------------
__global__ __launch_bounds__(256) void layernorm_split_kernel(
    const float* __restrict__ in, bf16* __restrict__ ohi, bf16* __restrict__ olo,
    const float* __restrict__ w, const float* __restrict__ b)
{
    int row = blockIdx.x;
    const float* xr = in + (size_t)row * DM;
    int t = threadIdx.x;
    float v0 = xr[t], v1 = xr[t + 256], v2 = xr[t + 512];
    float s  = v0 + v1 + v2;
    float sq = v0 * v0 + v1 * v1 + v2 * v2;
    #pragma unroll
    for (int o = 16; o > 0; o >>= 1) {
        s  += __shfl_xor_sync(0xFFFFFFFFu, s,  o);
        sq += __shfl_xor_sync(0xFFFFFFFFu, sq, o);
    }
    __shared__ float ss[8], sqs[8];
    int wid = t >> 5, lane = t & 31;
    if (lane == 0) { ss[wid] = s; sqs[wid] = sq; }
    __syncthreads();
    float ts = 0.f, tq = 0.f;
    #pragma unroll
    for (int i = 0; i < 8; i++) { ts += ss[i]; tq += sqs[i]; }
    float mean = ts * (1.0f / DM);
    float var  = tq * (1.0f / DM) - mean * mean;
    float rstd = rsqrtf(var + 1e-5f);
    size_t base = (size_t)row * DM;
    #pragma unroll
    for (int j = 0; j < 3; j++) {
        float v = (j == 0 ? v0 : (j == 1 ? v1 : v2));
        float y = (v - mean) * rstd * w[t + j * 256] + b[t + j * 256];
        bf16 h, l; split1(y, h, l);
        ohi[base + t + j * 256] = h;
        olo[base + t + j * 256] = l;
    }
}

// ---------------- fused 3-term HMMA bf16 split GEMM (3-stage pipeline) -------
#define GSTAGE 32768
#define GEMM_SMEM (3 * GSTAGE)
template <int EPI_ADD>
__global__ __launch_bounds__(256) void mma_gemm_kernel(
    const bf16* __restrict__ Ah, const bf16* __restrict__ Al,
    const bf16* __restrict__ Bh, const bf16* __restrict__ Bl,
    const float* __restrict__ Cin, float* __restrict__ C,
    int M, int N, int K)
{
    extern __shared__ __align__(16) char dynsmem[];
    uint32_t sS = smem_u32(dynsmem);

    int tid = threadIdx.x, wid = tid >> 5, lane = tid & 31;
    int bm = blockIdx.y * 128, bn = blockIdx.x * 128;
    int wm = (wid & 1) * 64;
    int wn = (wid >> 1) * 32;

    float acc[4][4][4];
    #pragma unroll
    for (int i = 0; i < 4; i++)
        #pragma unroll
        for (int j = 0; j < 4; j++)
            #pragma unroll
            for (int q = 0; q < 4; q++) acc[i][j][q] = 0.f;

    const int T = K >> 5;

    int r0c = (tid * 2) >> 2;
    int c0c = (tid * 2) & 3;
    int r1c = (tid * 2 + 1) >> 2;
    int c1c = (tid * 2 + 1) & 3;
    uint32_t swA0 = (uint32_t)(r0c * 64 + ((c0c ^ (r0c & 3)) << 4));
    uint32_t swA1 = (uint32_t)(r1c * 64 + ((c1c ^ (r1c & 3)) << 4));

    auto issue = [&](int t) {
        int k0 = t << 5;
        uint32_t st = sS + (uint32_t)((t % 3) * GSTAGE);
        size_t a0 = (size_t)(bm + r0c) * K + k0;
        size_t a1 = (size_t)(bm + r1c) * K + k0;
        size_t b0 = (size_t)(bn + r0c) * K + k0;
        size_t b1 = (size_t)(bn + r1c) * K + k0;
        cp16(st + 0     + swA0, Ah + a0 + c0c * 8);
        cp16(st + 0     + swA1, Ah + a1 + c1c * 8);
        cp16(st + 8192  + swA0, Al + a0 + c0c * 8);
        cp16(st + 8192  + swA1, Al + a1 + c1c * 8);
        cp16(st + 16384 + swA0, Bh + b0 + c0c * 8);
        cp16(st + 16384 + swA1, Bh + b1 + c1c * 8);
        cp16(st + 24576 + swA0, Bl + b0 + c0c * 8);
        cp16(st + 24576 + swA1, Bl + b1 + c1c * 8);
        CP_COMMIT();
    };

    issue(0);
    issue(1);
    for (int t = 0; t < T; t++) {
        if (t + 2 < T) { issue(t + 2); CP_WAIT2(); }
        else if (t + 1 < T) { CP_WAIT1(); }
        else { CP_WAIT0(); }
        __syncthreads();

        uint32_t st = sS + (uint32_t)((t % 3) * GSTAGE);

        #pragma unroll
        for (int ks = 0; ks < 2; ks++) {
            uint32_t aH[4][4], aL[4][4];
            #pragma unroll
            for (int mt = 0; mt < 4; mt++) {
                int row = wm + mt * 16 + (lane & 15);
                int c = (ks * 16 + ((lane >> 4) << 3)) >> 3;
                uint32_t off = (uint32_t)(row * 64 + ((c ^ (row & 3)) << 4));
                ldsm4(aH[mt][0], aH[mt][1], aH[mt][2], aH[mt][3], st + off);
                ldsm4(aL[mt][0], aL[mt][1], aL[mt][2], aL[mt][3], st + 8192 + off);
            }
            uint32_t bH[4][2], bL[4][2];
            #pragma unroll
            for (int p = 0; p < 2; p++) {
                int n = wn + p * 16 + (lane & 7) + ((lane >> 4) << 3);
                int c = (ks * 16 + (((lane >> 3) & 1) << 3)) >> 3;
                uint32_t off = (uint32_t)(n * 64 + ((c ^ (n & 3)) << 4));
                ldsm4(bH[2 * p][0], bH[2 * p][1], bH[2 * p + 1][0], bH[2 * p + 1][1],
                      st + 16384 + off);
                ldsm4(bL[2 * p][0], bL[2 * p][1], bL[2 * p + 1][0], bL[2 * p + 1][1],
                      st + 24576 + off);
            }
            #pragma unroll
            for (int mt = 0; mt < 4; mt++)
                #pragma unroll
                for (int nt = 0; nt < 4; nt++) {
                    mma16816(acc[mt][nt], aH[mt], bH[nt]);
                    mma16816(acc[mt][nt], aH[mt], bL[nt]);
                    mma16816(acc[mt][nt], aL[mt], bH[nt]);
                }
        }
        __syncthreads();
    }

    int grp = lane >> 2, tig = lane & 3;
    #pragma unroll
    for (int mt = 0; mt < 4; mt++) {
        #pragma unroll
        for (int nt = 0; nt < 4; nt++) {
            int row = bm + wm + mt * 16 + grp;
            int col = bn + wn + nt * 8 + tig * 2;
            float2 v0, v1;
            v0.x = acc[mt][nt][0]; v0.y = acc[mt][nt][1];
            v1.x = acc[mt][nt][2]; v1.y = acc[mt][nt][3];
            size_t o0 = (size_t)row * N + col;
            size_t o1 = (size_t)(row + 8) * N + col;
            if (EPI_ADD) {
                float2 c0 = *(const float2*)&Cin[o0];
                float2 c1 = *(const float2*)&Cin[o1];
                v0.x += c0.x; v0.y += c0.y;
                v1.x += c1.x; v1.y += c1.y;
            }
            *(float2*)&C[o0] = v0;
            *(float2*)&C[o1] = v1;
        }
    }
}

// ---------------- flash attention partial (KV-split, ALiBi, f32x2) ----------
// grid (SEQ/128, NH, BATCH*NSPLIT). Each block handles 128 queries over a
// 256-key span; writes unnormalized o and (m, l) partials.
__global__ __launch_bounds__(128) void flash_attn_partial_kernel(
    const float* __restrict__ qkv, const float* __restrict__ log_slopes,
    float* __restrict__ opart, float2* __restrict__ mlpart)
{
    const int QW = 3 * DM;
    const int HD2 = HDIM / 2;
    int qt = blockIdx.x, h = blockIdx.y;
    int b  = blockIdx.z / NSPLIT;
    int sp = blockIdx.z - b * NSPLIT;
    int t  = threadIdx.x;
    int q_idx = qt * 128 + t;

    float slope = __expf(log_slopes[h]);
    const float scale = 0.14433756729740643f;

    const float* qrow = qkv + (size_t)(b * SEQ + q_idx) * QW + h * HDIM;
    u64 q2[HD2];
    #pragma unroll
    for (int d = 0; d < HD2; d += 2) {
        double2 v = *(const double2*)(qrow + 2 * d);
        q2[d]     = __double_as_longlong(v.x);
        q2[d + 1] = __double_as_longlong(v.y);
    }

    u64 o2[HD2];
    #pragma unroll
    for (int d = 0; d < HD2; d++) o2[d] = 0ull;
    float m = -INFINITY, l = 0.f;

    __shared__ __align__(16) float Ks[64][HDIM];
    __shared__ __align__(16) float Vs[64][HDIM];

    const int kt0 = sp * (SEQ / 64 / NSPLIT);         // 4 tiles per split
    for (int kt = kt0; kt < kt0 + SEQ / 64 / NSPLIT; kt++) {
        __syncthreads();
        #pragma unroll
        for (int i = 0; i < 6; i++) {
            int idx = t * 6 + i;
            int r = idx / 12;
            int c = (idx % 12) * 4;
            const float* krow = qkv + (size_t)(b * SEQ + kt * 64 + r) * QW
                                + DM + h * HDIM + c;
            *(float4*)&Ks[r][c] = *(const float4*)krow;
            *(float4*)&Vs[r][c] = *(const float4*)(krow + DM);
        }
        __syncthreads();

        #pragma unroll 1
        for (int j0 = 0; j0 < 64; j0 += 8) {
            float sc[8];
            #pragma unroll
            for (int jj = 0; jj < 8; jj++) {
                const float* kr = &Ks[j0 + jj][0];
                u64 acc0 = 0ull, acc1 = 0ull;
                #pragma unroll
                for (int d = 0; d < HD2; d += 2) {
                    double2 kv = *(const double2*)(kr + 2 * d);
                    ffma2(acc0, q2[d],     __double_as_longlong(kv.x));
                    ffma2(acc1, q2[d + 1], __double_as_longlong(kv.y));
                }
                float2 s0 = unpack2(acc0);
                float2 s1 = unpack2(acc1);
                int kpos = kt * 64 + j0 + jj;
                sc[jj] = (s0.x + s0.y + s1.x + s1.y) * scale
                         - slope * fabsf((float)(q_idx - kpos));
            }
            float mt = m;
            #pragma unroll
            for (int jj = 0; jj < 8; jj++) mt = fmaxf(mt, sc[jj]);
            float corr = __expf(m - mt);
            m = mt;
            l *= corr;
            u64 corr2 = pack2(corr);
            #pragma unroll
            for (int d = 0; d < HD2; d++) o2[d] = fmul2(o2[d], corr2);
            #pragma unroll
            for (int jj = 0; jj < 8; jj++) {
                float p = __expf(sc[jj] - m);
                l += p;
                u64 p2 = pack2(p);
                const float* vr = &Vs[j0 + jj][0];
                #pragma unroll
                for (int d = 0; d < HD2; d += 2) {
                    double2 vv = *(const double2*)(vr + 2 * d);
                    ffma2(o2[d],     p2, __double_as_longlong(vv.x));
                    ffma2(o2[d + 1], p2, __double_as_longlong(vv.y));
                }
            }
        }
    }

    size_t prow = (size_t)sp * MTOK + (size_t)b * SEQ + q_idx;
    float* orow = opart + prow * DM + h * HDIM;
    #pragma unroll
    for (int d = 0; d < HD2; d += 2) {
        double2 ov;
        ov.x = __longlong_as_double(o2[d]);
        ov.y = __longlong_as_double(o2[d + 1]);
        *(double2*)(orow + 2 * d) = ov;
    }
    mlpart[prow * NH + h] = make_float2(m, l);
}

// ---------------- combine attention partials + bf16 split --------------------
// grid = MTOK blocks of 192 threads; each thread owns 4 consecutive d (one head).
__global__ __launch_bounds__(192) void attn_combine_kernel(
    const float* __restrict__ opart, const float2* __restrict__ mlpart,
    bf16* __restrict__ out_hi, bf16* __restrict__ out_lo)
{
    int row = blockIdx.x;
    int t = threadIdx.x;
    int d0 = t * 4;
    int h = d0 / HDIM;

    float ms[NSPLIT];
    float mmax = -INFINITY;
    float ls[NSPLIT];
    #pragma unroll
    for (int sp = 0; sp < NSPLIT; sp++) {
        float2 ml = mlpart[((size_t)sp * MTOK + row) * NH + h];
        ms[sp] = ml.x; ls[sp] = ml.y;
        mmax = fmaxf(mmax, ml.x);
    }
    float L = 0.f;
    float w[NSPLIT];
    #pragma unroll
    for (int sp = 0; sp < NSPLIT; sp++) {
        w[sp] = __expf(ms[sp] - mmax);
        L += ls[sp] * w[sp];
    }
    float inv = 1.0f / L;

    float4 acc = make_float4(0.f, 0.f, 0.f, 0.f);
    #pragma unroll
    for (int sp = 0; sp < NSPLIT; sp++) {
        float4 v = *(const float4*)&opart[((size_t)sp * MTOK + row) * DM + d0];
        acc.x += v.x * w[sp]; acc.y += v.y * w[sp];
        acc.z += v.z * w[sp]; acc.w += v.w * w[sp];
    }
    acc.x *= inv; acc.y *= inv; acc.z *= inv; acc.w *= inv;

    bf16 h0, l0, h1, l1, h2, l2, h3, l3;
    split1(acc.x, h0, l0); split1(acc.y, h1, l1);
    split1(acc.z, h2, l2); split1(acc.w, h3, l3);
    bf162 H0; H0.x = h0; H0.y = h1;
    bf162 H1; H1.x = h2; H1.y = h3;
    bf162 L0; L0.x = l0; L0.y = l1;
    bf162 L1; L1.x = l2; L1.y = l3;
    size_t base = (size_t)row * DM + d0;
    *(bf162*)(out_hi + base)     = H0;
    *(bf162*)(out_hi + base + 2) = H1;
    *(bf162*)(out_lo + base)     = L0;
    *(bf162*)(out_lo + base + 2) = L1;
}

// ---------------- silu(gate)*up with fused bf16 split ------------------------
__global__ void silu_split_kernel(const float4* __restrict__ g,
                                  const float4* __restrict__ u,
                                  bf162* __restrict__ ohi, bf162* __restrict__ olo,
                                  int n4)
{
    int i = blockIdx.x * blockDim.x + threadIdx.x;
    if (i >= n4) return;
    float4 gv = g[i], uv = u[i];
    float y0 = uv.x * gv.x / (1.0f + __expf(-gv.x));
    float y1 = uv.y * gv.y / (1.0f + __expf(-gv.y));
    float y2 = uv.z * gv.z / (1.0f + __expf(-gv.z));
    float y3 = uv.w * gv.w / (1.0f + __expf(-gv.w));
    bf16 h0, l0, h1, l1, h2, l2, h3, l3;
    split1(y0, h0, l0); split1(y1, h1, l1);
    split1(y2, h2, l2); split1(y3, h3, l3);
    bf162 H0; H0.x = h0; H0.y = h1;
    bf162 H1; H1.x = h2; H1.y = h3;
    bf162 L0; L0.x = l0; L0.y = l1;
    bf162 L1; L1.x = l2; L1.y = l3;
    ohi[i * 2] = H0; ohi[i * 2 + 1] = H1;
    olo[i * 2] = L0; olo[i * 2 + 1] = L1;
}

// ---------------- host orchestration ----------------------------------------
static void run_gemm(int epi, const bf16* ah, const bf16* al,
                     const bf16* bh, const bf16* bl,
                     const float* cin, float* c, int M, int N, int K)
{
    dim3 grid(N / 128, M / 128);
    if (epi)
        mma_gemm_kernel<1><<<grid, 256, GEMM_SMEM>>>(ah, al, bh, bl, cin, c, M, N, K);
    else
        mma_gemm_kernel<0><<<grid, 256, GEMM_SMEM>>>(ah, al, bh, bl, cin, c, M, N, K);
}

extern "C" void kernel_launch(void* const* d_in, const int* in_sizes, int n_in,
                              void* d_out, int out_size)
{
    const float* cls_tokens = (const float*)d_in[0];
    const float* cls_token  = (const float*)d_in[1];
    const float* log_slopes = (const float*)d_in[2];
    const float* Wqkv       = (const float*)d_in[3];
    const float* Wo         = (const float*)d_in[4];
    const float* Wg         = (const float*)d_in[5];
    const float* Wu         = (const float*)d_in[6];
    const float* Wd         = (const float*)d_in[7];
    const float* ln1w       = (const float*)d_in[8];
    const float* ln1b       = (const float*)d_in[9];
    const float* ln2w       = (const float*)d_in[10];
    const float* ln2b       = (const float*)d_in[11];
    const float* finw       = (const float*)d_in[12];
    const float* finb       = (const float*)d_in[13];
    float* out = (float*)d_out;

    cudaFuncSetAttribute(mma_gemm_kernel<0>,
                         cudaFuncAttributeMaxDynamicSharedMemorySize, GEMM_SMEM);
    cudaFuncSetAttribute(mma_gemm_kernel<1>,
                         cudaFuncAttributeMaxDynamicSharedMemorySize, GEMM_SMEM);

    float *x, *qkv, *gate, *up, *opart;
    float2 *mlpart;
    bf16 *h_hi, *h_lo, *at_hi, *at_lo, *gg_hi, *gg_lo;
    bf16 *wqkv_hi, *wqkv_lo, *wo_hi, *wo_lo, *wg_hi, *wg_lo,
         *wu_hi, *wu_lo, *wd_hi, *wd_lo;
    cudaGetSymbolAddress((void**)&x,    g_x);
    cudaGetSymbolAddress((void**)&qkv,  g_qkv);
    cudaGetSymbolAddress((void**)&gate, g_gate);
    cudaGetSymbolAddress((void**)&up,   g_up);
    cudaGetSymbolAddress((void**)&opart, g_opart);
    cudaGetSymbolAddress((void**)&mlpart, g_mlpart);
    cudaGetSymbolAddress((void**)&h_hi, g_h_hi);
    cudaGetSymbolAddress((void**)&h_lo, g_h_lo);
    cudaGetSymbolAddress((void**)&at_hi, g_at_hi);
    cudaGetSymbolAddress((void**)&at_lo, g_at_lo);
    cudaGetSymbolAddress((void**)&gg_hi, g_g_hi);
    cudaGetSymbolAddress((void**)&gg_lo, g_g_lo);
    cudaGetSymbolAddress((void**)&wqkv_hi, g_wqkv_hi);
    cudaGetSymbolAddress((void**)&wqkv_lo, g_wqkv_lo);
    cudaGetSymbolAddress((void**)&wo_hi, g_wo_hi);
    cudaGetSymbolAddress((void**)&wo_lo, g_wo_lo);
    cudaGetSymbolAddress((void**)&wg_hi, g_wg_hi);
    cudaGetSymbolAddress((void**)&wg_lo, g_wg_lo);
    cudaGetSymbolAddress((void**)&wu_hi, g_wu_hi);
    cudaGetSymbolAddress((void**)&wu_lo, g_wu_lo);
    cudaGetSymbolAddress((void**)&wd_hi, g_wd_hi);
    cudaGetSymbolAddress((void**)&wd_lo, g_wd_lo);

    // weight conversion (fp32 -> bf16 hi/lo), once per launch
    {
        int n;
        n = LAYERS * 3 * DM * DM / 4;
        split4_kernel<<<(n + 255) / 256, 256>>>((const float4*)Wqkv,
            (bf162*)wqkv_hi, (bf162*)wqkv_lo, n);
        n = LAYERS * DM * DM / 4;
        split4_kernel<<<(n + 255) / 256, 256>>>((const float4*)Wo,
            (bf162*)wo_hi, (bf162*)wo_lo, n);
        n = LAYERS * FFDIM * DM / 4;
        split4_kernel<<<(n + 255) / 256, 256>>>((const float4*)Wg,
            (bf162*)wg_hi, (bf162*)wg_lo, n);
        split4_kernel<<<(n + 255) / 256, 256>>>((const float4*)Wu,
            (bf162*)wu_hi, (bf162*)wu_lo, n);
        n = LAYERS * DM * FFDIM / 4;
        split4_kernel<<<(n + 255) / 256, 256>>>((const float4*)Wd,
            (bf162*)wd_hi, (bf162*)wd_lo, n);
    }

    build_x_kernel<<<(MTOK * DM + 255) / 256, 256>>>(cls_tokens, cls_token, x);

    for (int l = 0; l < LAYERS; l++) {
        size_t oq = (size_t)l * 3 * DM * DM;
        size_t oo = (size_t)l * DM * DM;
        size_t og = (size_t)l * FFDIM * DM;
        size_t od = (size_t)l * DM * FFDIM;

        layernorm_split_kernel<<<MTOK, 256>>>(x, h_hi, h_lo,
                                              ln1w + l * DM, ln1b + l * DM);

        run_gemm(0, h_hi, h_lo, wqkv_hi + oq, wqkv_lo + oq,
                 nullptr, qkv, MTOK, 3 * DM, DM);

        flash_attn_partial_kernel<<<dim3(SEQ / 128, NH, BATCH * NSPLIT), 128>>>(
            qkv, log_slopes, opart, mlpart);
        attn_combine_kernel<<<MTOK, 192>>>(opart, mlpart, at_hi, at_lo);

        run_gemm(1, at_hi, at_lo, wo_hi + oo, wo_lo + oo,
                 x, x, MTOK, DM, DM);

        layernorm_split_kernel<<<MTOK, 256>>>(x, h_hi, h_lo,
                                              ln2w + l * DM, ln2b + l * DM);

        run_gemm(0, h_hi, h_lo, wg_hi + og, wg_lo + og,
                 nullptr, gate, MTOK, FFDIM, DM);
        run_gemm(0, h_hi, h_lo, wu_hi + og, wu_lo + og,
                 nullptr, up, MTOK, FFDIM, DM);

        int n4 = MTOK * FFDIM / 4;
        silu_split_kernel<<<(n4 + 255) / 256, 256>>>(
            (const float4*)gate, (const float4*)up,
            (bf162*)gg_hi, (bf162*)gg_lo, n4);

        run_gemm(1, gg_hi, gg_lo, wd_hi + od, wd_lo + od,
                 x, x, MTOK, DM, FFDIM);
    }

    layernorm_kernel<<<BATCH, 256>>>(x, (size_t)SEQ * DM, out, finw, finb);
}

// round 11
// speedup vs baseline: 2.6438x; 1.2793x over previous
#include <cuda_runtime.h>
#include <cuda_bf16.h>
#include <math.h>
#include <stdint.h>
#include <string.h>

// ---------------- problem constants ----------------
#define LAYERS 6
#define BATCH  4
#define SEQ    1024
#define DM     768
#define NH     16
#define HDIM   48
#define FFDIM  3072
#define MTOK   (BATCH*SEQ)   // 4096

typedef unsigned long long u64;
typedef __nv_bfloat16  bf16;
typedef __nv_bfloat162 bf162;

// ---------------- mma.sync / ldmatrix / cp.async helpers --------------------
__device__ __forceinline__ uint32_t smem_u32(const void* p) {
    uint32_t a;
    asm("{ .reg .u64 t; cvta.to.shared.u64 t, %1; cvt.u32.u64 %0, t; }"
        : "=r"(a) : "l"(p));
    return a;
}
__device__ __forceinline__ void cp16(uint32_t dst, const void* src) {
    asm volatile("cp.async.cg.shared.global [%0], [%1], 16;" :: "r"(dst), "l"(src));
}
#define CP_COMMIT() asm volatile("cp.async.commit_group;" ::: "memory")
#define CP_WAIT2()  asm volatile("cp.async.wait_group 2;" ::: "memory")
#define CP_WAIT1()  asm volatile("cp.async.wait_group 1;" ::: "memory")
#define CP_WAIT0()  asm volatile("cp.async.wait_group 0;" ::: "memory")

__device__ __forceinline__ void ldsm4(uint32_t &r0, uint32_t &r1,
                                      uint32_t &r2, uint32_t &r3, uint32_t addr) {
    asm volatile("ldmatrix.sync.aligned.m8n8.x4.shared.b16 {%0,%1,%2,%3}, [%4];"
                 : "=r"(r0), "=r"(r1), "=r"(r2), "=r"(r3) : "r"(addr));
}
__device__ __forceinline__ void ldsm4t(uint32_t &r0, uint32_t &r1,
                                       uint32_t &r2, uint32_t &r3, uint32_t addr) {
    asm volatile("ldmatrix.sync.aligned.m8n8.x4.trans.shared.b16 {%0,%1,%2,%3}, [%4];"
                 : "=r"(r0), "=r"(r1), "=r"(r2), "=r"(r3) : "r"(addr));
}
__device__ __forceinline__ void mma16816(float* d, const uint32_t* a,
                                         const uint32_t* b) {
    asm volatile("mma.sync.aligned.m16n8k16.row.col.f32.bf16.bf16.f32 "
        "{%0,%1,%2,%3}, {%4,%5,%6,%7}, {%8,%9}, {%0,%1,%2,%3};"
        : "+f"(d[0]), "+f"(d[1]), "+f"(d[2]), "+f"(d[3])
        : "r"(a[0]), "r"(a[1]), "r"(a[2]), "r"(a[3]), "r"(b[0]), "r"(b[1]));
}

// ---------------- scratch (device globals) ----------------------------------
__device__ __align__(16) float g_x   [MTOK*DM];
__device__ __align__(16) float g_gate[MTOK*FFDIM];
__device__ __align__(16) float g_up  [MTOK*FFDIM];

__device__ __align__(16) bf16 g_qkvh[MTOK*3*DM];
__device__ __align__(16) bf16 g_qkvl[MTOK*3*DM];

__device__ __align__(16) bf16 g_h_hi [MTOK*DM];
__device__ __align__(16) bf16 g_h_lo [MTOK*DM];
__device__ __align__(16) bf16 g_at_hi[MTOK*DM];
__device__ __align__(16) bf16 g_at_lo[MTOK*DM];
__device__ __align__(16) bf16 g_g_hi [MTOK*FFDIM];
__device__ __align__(16) bf16 g_g_lo [MTOK*FFDIM];

__device__ __align__(16) bf16 g_wqkv_hi[LAYERS*3*DM*DM];
__device__ __align__(16) bf16 g_wqkv_lo[LAYERS*3*DM*DM];
__device__ __align__(16) bf16 g_wo_hi  [LAYERS*DM*DM];
__device__ __align__(16) bf16 g_wo_lo  [LAYERS*DM*DM];
__device__ __align__(16) bf16 g_wg_hi  [LAYERS*FFDIM*DM];
__device__ __align__(16) bf16 g_wg_lo  [LAYERS*FFDIM*DM];
__device__ __align__(16) bf16 g_wu_hi  [LAYERS*FFDIM*DM];
__device__ __align__(16) bf16 g_wu_lo  [LAYERS*FFDIM*DM];
__device__ __align__(16) bf16 g_wd_hi  [LAYERS*DM*FFDIM];
__device__ __align__(16) bf16 g_wd_lo  [LAYERS*DM*FFDIM];

// ---------------- split helpers ---------------------------------------------
__device__ __forceinline__ void split1(float x, bf16 &h, bf16 &l) {
    h = __float2bfloat16(x);
    l = __float2bfloat16(x - __bfloat162float(h));
}

__global__ void split4_kernel(const float4* __restrict__ in,
                              bf162* __restrict__ hi, bf162* __restrict__ lo,
                              int n4)
{
    int i = blockIdx.x * blockDim.x + threadIdx.x;
    if (i >= n4) return;
    float4 v = in[i];
    bf16 h0, l0, h1, l1, h2, l2, h3, l3;
    split1(v.x, h0, l0); split1(v.y, h1, l1);
    split1(v.z, h2, l2); split1(v.w, h3, l3);
    bf162 H0; H0.x = h0; H0.y = h1;
    bf162 H1; H1.x = h2; H1.y = h3;
    bf162 L0; L0.x = l0; L0.y = l1;
    bf162 L1; L1.x = l2; L1.y = l3;
    hi[i * 2] = H0; hi[i * 2 + 1] = H1;
    lo[i * 2] = L0; lo[i * 2 + 1] = L1;
}

// ---------------- build x ----------------------------------------------------
__global__ void build_x_kernel(const float* __restrict__ cls_tokens,
                               const float* __restrict__ cls_token,
                               float* __restrict__ x)
{
    int idx = blockIdx.x * blockDim.x + threadIdx.x;
    if (idx >= MTOK * DM) return;
    int row = idx / DM;
    int d   = idx - row * DM;
    int b   = row >> 10;
    int s   = row & (SEQ - 1);
    float v;
    if (s == 0) v = cls_token[d];
    else        v = cls_tokens[((b * (SEQ - 1)) + (s - 1)) * DM + d];
    x[idx] = v;
}

// ---------------- layernorm (fp32 out) ---------------------------------------
__global__ __launch_bounds__(256) void layernorm_kernel(
    const float* __restrict__ in, size_t in_stride, float* __restrict__ out,
    const float* __restrict__ w, const float* __restrict__ b)
{
    int row = blockIdx.x;
    const float* xr = in + (size_t)row * in_stride;
    int t = threadIdx.x;
    float v0 = xr[t], v1 = xr[t + 256], v2 = xr[t + 512];
    float s  = v0 + v1 + v2;
    float sq = v0 * v0 + v1 * v1 + v2 * v2;
    #pragma unroll
    for (int o = 16; o > 0; o >>= 1) {
        s  += __shfl_xor_sync(0xFFFFFFFFu, s,  o);
        sq += __shfl_xor_sync(0xFFFFFFFFu, sq, o);
    }
    __shared__ float ss[8], sqs[8];
    int wid = t >> 5, lane = t & 31;
    if (lane == 0) { ss[wid] = s; sqs[wid] = sq; }
    __syncthreads();
    float ts = 0.f, tq = 0.f;
    #pragma unroll
    for (int i = 0; i < 8; i++) { ts += ss[i]; tq += sqs[i]; }
    float mean = ts * (1.0f / DM);
    float var  = tq * (1.0f / DM) - mean * mean;
    float rstd = rsqrtf(var + 1e-5f);
    float* orow = out + (size_t)row * DM;
    orow[t]       = (v0 - mean) * rstd * w[t]       + b[t];
    orow[t + 256] = (v1 - mean) * rstd * w[t + 256] + b[t + 256];
    orow[t + 512] = (v2 - mean) * rstd * w[t + 512] + b[t + 512];
}

// ---------------- layernorm with fused bf16 hi/lo split ----------------------
__global__ __launch_bounds__(256) void layernorm_split_kernel(
    const float* __restrict__ in, bf16* __restrict__ ohi, bf16* __restrict__ olo,
    const float* __restrict__ w, const float* __restrict__ b)
{
    int row = blockIdx.x;
    const float* xr = in + (size_t)row * DM;
    int t = threadIdx.x;
    float v0 = xr[t], v1 = xr[t + 256], v2 = xr[t + 512];
    float s  = v0 + v1 + v2;
    float sq = v0 * v0 + v1 * v1 + v2 * v2;
    #pragma unroll
    for (int o = 16; o > 0; o >>= 1) {
        s  += __shfl_xor_sync(0xFFFFFFFFu, s,  o);
        sq += __shfl_xor_sync(0xFFFFFFFFu, sq, o);
    }
    __shared__ float ss[8], sqs[8];
    int wid = t >> 5, lane = t & 31;
    if (lane == 0) { ss[wid] = s; sqs[wid] = sq; }
    __syncthreads();
    float ts = 0.f, tq = 0.f;
    #pragma unroll
    for (int i = 0; i < 8; i++) { ts += ss[i]; tq += sqs[i]; }
    float mean = ts * (1.0f / DM);
    float var  = tq * (1.0f / DM) - mean * mean;
    float rstd = rsqrtf(var + 1e-5f);
    size_t base = (size_t)row * DM;
    #pragma unroll
    for (int j = 0; j < 3; j++) {
        float v = (j == 0 ? v0 : (j == 1 ? v1 : v2));
        float y = (v - mean) * rstd * w[t + j * 256] + b[t + j * 256];
        bf16 h, l; split1(y, h, l);
        ohi[base + t + j * 256] = h;
        olo[base + t + j * 256] = l;
    }
}

// ---------------- fused 3-term HMMA bf16 split GEMM (3-stage pipeline) -------
// EPI_MODE: 0 = store fp32, 1 = add Cin + store fp32, 2 = split-store bf16 hi/lo
#define GSTAGE 32768
#define GEMM_SMEM (3 * GSTAGE)
template <int EPI_MODE>
__global__ __launch_bounds__(256) void mma_gemm_kernel(
    const bf16* __restrict__ Ah, const bf16* __restrict__ Al,
    const bf16* __restrict__ Bh, const bf16* __restrict__ Bl,
    const float* __restrict__ Cin, float* __restrict__ C,
    bf16* __restrict__ Chi, bf16* __restrict__ Clo,
    int M, int N, int K)
{
    extern __shared__ __align__(16) char dynsmem[];
    uint32_t sS = smem_u32(dynsmem);

    int tid = threadIdx.x, wid = tid >> 5, lane = tid & 31;
    int bm = blockIdx.y * 128, bn = blockIdx.x * 128;
    int wm = (wid & 1) * 64;
    int wn = (wid >> 1) * 32;

    float acc[4][4][4];
    #pragma unroll
    for (int i = 0; i < 4; i++)
        #pragma unroll
        for (int j = 0; j < 4; j++)
            #pragma unroll
            for (int q = 0; q < 4; q++) acc[i][j][q] = 0.f;

    const int T = K >> 5;

    int r0c = (tid * 2) >> 2;
    int c0c = (tid * 2) & 3;
    int r1c = (tid * 2 + 1) >> 2;
    int c1c = (tid * 2 + 1) & 3;
    uint32_t swA0 = (uint32_t)(r0c * 64 + ((c0c ^ (r0c & 3)) << 4));
    uint32_t swA1 = (uint32_t)(r1c * 64 + ((c1c ^ (r1c & 3)) << 4));

    auto issue = [&](int t) {
        int k0 = t << 5;
        uint32_t st = sS + (uint32_t)((t % 3) * GSTAGE);
        size_t a0 = (size_t)(bm + r0c) * K + k0;
        size_t a1 = (size_t)(bm + r1c) * K + k0;
        size_t b0 = (size_t)(bn + r0c) * K + k0;
        size_t b1 = (size_t)(bn + r1c) * K + k0;
        cp16(st + 0     + swA0, Ah + a0 + c0c * 8);
        cp16(st + 0     + swA1, Ah + a1 + c1c * 8);
        cp16(st + 8192  + swA0, Al + a0 + c0c * 8);
        cp16(st + 8192  + swA1, Al + a1 + c1c * 8);
        cp16(st + 16384 + swA0, Bh + b0 + c0c * 8);
        cp16(st + 16384 + swA1, Bh + b1 + c1c * 8);
        cp16(st + 24576 + swA0, Bl + b0 + c0c * 8);
        cp16(st + 24576 + swA1, Bl + b1 + c1c * 8);
        CP_COMMIT();
    };

    issue(0);
    issue(1);
    for (int t = 0; t < T; t++) {
        if (t + 2 < T) { issue(t + 2); CP_WAIT2(); }
        else if (t + 1 < T) { CP_WAIT1(); }
        else { CP_WAIT0(); }
        __syncthreads();

        uint32_t st = sS + (uint32_t)((t % 3) * GSTAGE);

        #pragma unroll
        for (int ks = 0; ks < 2; ks++) {
            uint32_t aH[4][4], aL[4][4];
            #pragma unroll
            for (int mt = 0; mt < 4; mt++) {
                int row = wm + mt * 16 + (lane & 15);
                int c = (ks * 16 + ((lane >> 4) << 3)) >> 3;
                uint32_t off = (uint32_t)(row * 64 + ((c ^ (row & 3)) << 4));
                ldsm4(aH[mt][0], aH[mt][1], aH[mt][2], aH[mt][3], st + off);
                ldsm4(aL[mt][0], aL[mt][1], aL[mt][2], aL[mt][3], st + 8192 + off);
            }
            uint32_t bH[4][2], bL[4][2];
            #pragma unroll
            for (int p = 0; p < 2; p++) {
                int n = wn + p * 16 + (lane & 7) + ((lane >> 4) << 3);
                int c = (ks * 16 + (((lane >> 3) & 1) << 3)) >> 3;
                uint32_t off = (uint32_t)(n * 64 + ((c ^ (n & 3)) << 4));
                ldsm4(bH[2 * p][0], bH[2 * p][1], bH[2 * p + 1][0], bH[2 * p + 1][1],
                      st + 16384 + off);
                ldsm4(bL[2 * p][0], bL[2 * p][1], bL[2 * p + 1][0], bL[2 * p + 1][1],
                      st + 24576 + off);
            }
            #pragma unroll
            for (int mt = 0; mt < 4; mt++)
                #pragma unroll
                for (int nt = 0; nt < 4; nt++) {
                    mma16816(acc[mt][nt], aH[mt], bH[nt]);
                    mma16816(acc[mt][nt], aH[mt], bL[nt]);
                    mma16816(acc[mt][nt], aL[mt], bH[nt]);
                }
        }
        __syncthreads();
    }

    int grp = lane >> 2, tig = lane & 3;
    #pragma unroll
    for (int mt = 0; mt < 4; mt++) {
        #pragma unroll
        for (int nt = 0; nt < 4; nt++) {
            int row = bm + wm + mt * 16 + grp;
            int col = bn + wn + nt * 8 + tig * 2;
            size_t o0 = (size_t)row * N + col;
            size_t o1 = (size_t)(row + 8) * N + col;
            float2 v0, v1;
            v0.x = acc[mt][nt][0]; v0.y = acc[mt][nt][1];
            v1.x = acc[mt][nt][2]; v1.y = acc[mt][nt][3];
            if (EPI_MODE == 1) {
                float2 c0 = *(const float2*)&Cin[o0];
                float2 c1 = *(const float2*)&Cin[o1];
                v0.x += c0.x; v0.y += c0.y;
                v1.x += c1.x; v1.y += c1.y;
            }
            if (EPI_MODE == 2) {
                bf16 h0, l0, h1, l1;
                split1(v0.x, h0, l0); split1(v0.y, h1, l1);
                bf162 H0; H0.x = h0; H0.y = h1;
                bf162 L0; L0.x = l0; L0.y = l1;
                *(bf162*)(Chi + o0) = H0;
                *(bf162*)(Clo + o0) = L0;
                split1(v1.x, h0, l0); split1(v1.y, h1, l1);
                bf162 H1; H1.x = h0; H1.y = h1;
                bf162 L1; L1.x = l0; L1.y = l1;
                *(bf162*)(Chi + o1) = H1;
                *(bf162*)(Clo + o1) = L1;
            } else {
                *(float2*)&C[o0] = v0;
                *(float2*)&C[o1] = v1;
            }
        }
    }
}

// ---------------- HMMA flash attention (split bf16, ALiBi) -------------------
// grid (SEQ/128, NH, BATCH), 128 threads (4 warps x 32 queries each).
// Q fragments register-resident; K/V hi/lo double-buffered via cp.async.
// S = Qh*Kh + Qh*Kl + Ql*Kh ; O += Ph*Vh + Ph*Vl + Pl*Vh.
#define ATT_SMEM 65536
__global__ __launch_bounds__(128) void flash_attn_mma_kernel(
    const bf16* __restrict__ qkh, const bf16* __restrict__ qkl,
    const float* __restrict__ log_slopes,
    bf16* __restrict__ out_hi, bf16* __restrict__ out_lo)
{
    extern __shared__ __align__(16) char asmem[];
    uint32_t sb = smem_u32(asmem);
    const int QW = 3 * DM;
    int qt = blockIdx.x, hh = blockIdx.y, b = blockIdx.z;
    int tid = threadIdx.x, wid = tid >> 5, lane = tid & 31;
    int wm = wid * 32;
    int grp = lane >> 2, tig = lane & 3;
    float slope = __expf(log_slopes[hh]);
    const float scale = 0.14433756729740643f;  // 1/sqrt(48)
    size_t rbase = (size_t)(b * SEQ + qt * 128);

    // ---- stage Q hi/lo into smem (128 rows x 48 d, 128B swizzled rows) ----
    #pragma unroll
    for (int i = 0; i < 6; i++) {
        int j = i * 128 + tid;          // 0..767
        int r = j / 6, c = j - r * 6;
        uint32_t dst = (uint32_t)(r * 128 + ((c ^ (r & 3)) << 4));
        size_t g = (rbase + r) * QW + hh * HDIM + c * 8;
        cp16(sb + dst, qkh + g);
        cp16(sb + 16384 + dst, qkl + g);
    }
    CP_COMMIT(); CP_WAIT0();
    __syncthreads();

    // extract Q fragments (A operand, m16k16): [mt][kstep][4]
    uint32_t qfh[2][3][4], qfl[2][3][4];
    #pragma unroll
    for (int mt = 0; mt < 2; mt++)
        #pragma unroll
        for (int ks = 0; ks < 3; ks++) {
            int r = wm + mt * 16 + (lane & 15);
            int c = ks * 2 + (lane >> 4);
            uint32_t off = (uint32_t)(r * 128 + ((c ^ (r & 3)) << 4));
            ldsm4(qfh[mt][ks][0], qfh[mt][ks][1], qfh[mt][ks][2], qfh[mt][ks][3],
                  sb + off);
            ldsm4(qfl[mt][ks][0], qfl[mt][ks][1], qfl[mt][ks][2], qfl[mt][ks][3],
                  sb + 16384 + off);
        }
    __syncthreads();

    float oacc[2][6][4];
    #pragma unroll
    for (int mt = 0; mt < 2; mt++)
        #pragma unroll
        for (int nt = 0; nt < 6; nt++)
            #pragma unroll
            for (int q = 0; q < 4; q++) oacc[mt][nt][q] = 0.f;
    float m_run[4], l_run[4];
    #pragma unroll
    for (int rr = 0; rr < 4; rr++) { m_run[rr] = -INFINITY; l_run[rr] = 0.f; }

    // K/V tile loader: stage = kt&1; layout per stage: Kh,Kl,Vh,Vl @ 8KB each
    auto issueKV = [&](int kt) {
        uint32_t st = sb + (uint32_t)((kt & 1) * 32768);
        #pragma unroll
        for (int i = 0; i < 12; i++) {
            int j = i * 128 + tid;                 // 0..1535
            int mat = j / 384;
            int rem = j - mat * 384;
            int rr = rem / 6;
            int cc = rem - rr * 6;
            uint32_t dst = st + (uint32_t)(mat * 8192)
                         + (uint32_t)(rr * 128 + ((cc ^ (rr & 3)) << 4));
            size_t g = (size_t)(b * SEQ + kt * 64 + rr) * QW + hh * HDIM
                     + ((mat < 2) ? DM : 2 * DM) + cc * 8;
            const bf16* src = (mat & 1) ? qkl : qkh;
            cp16(dst, src + g);
        }
        CP_COMMIT();
    };

    issueKV(0);
    for (int kt = 0; kt < SEQ / 64; kt++) {
        if (kt + 1 < SEQ / 64) { issueKV(kt + 1); CP_WAIT1(); }
        else                   { CP_WAIT0(); }
        __syncthreads();
        uint32_t st = sb + (uint32_t)((kt & 1) * 32768);

        // ---- S = Q K^T (3-term split) ----
        float s[2][8][4];
        #pragma unroll
        for (int mt = 0; mt < 2; mt++)
            #pragma unroll
            for (int nt = 0; nt < 8; nt++)
                #pragma unroll
                for (int q = 0; q < 4; q++) s[mt][nt][q] = 0.f;

        #pragma unroll
        for (int ks = 0; ks < 3; ks++) {
            uint32_t bh[8][2], bl[8][2];
            #pragma unroll
            for (int p = 0; p < 4; p++) {
                int n = p * 16 + (lane & 7) + ((lane >> 4) << 3);
                int c = ks * 2 + ((lane >> 3) & 1);
                uint32_t off = (uint32_t)(n * 128 + ((c ^ (n & 3)) << 4));
                ldsm4(bh[2*p][0], bh[2*p][1], bh[2*p+1][0], bh[2*p+1][1], st + off);
                ldsm4(bl[2*p][0], bl[2*p][1], bl[2*p+1][0], bl[2*p+1][1], st + 8192 + off);
            }
            #pragma unroll
            for (int mt = 0; mt < 2; mt++)
                #pragma unroll
                for (int nt = 0; nt < 8; nt++) {
                    mma16816(s[mt][nt], qfh[mt][ks], bh[nt]);
                    mma16816(s[mt][nt], qfh[mt][ks], bl[nt]);
                    mma16816(s[mt][nt], qfl[mt][ks], bh[nt]);
                }
        }

        // ---- online softmax (scale + ALiBi fused) ----
        float corr[4];
        #pragma unroll
        for (int rr = 0; rr < 4; rr++) {
            int mt = rr >> 1, half = rr & 1;
            int qrow = qt * 128 + wm + mt * 16 + half * 8 + grp;
            float mx = -INFINITY;
            #pragma unroll
            for (int nt = 0; nt < 8; nt++)
                #pragma unroll
                for (int jx = 0; jx < 2; jx++) {
                    int c = half * 2 + jx;
                    int kcol = kt * 64 + nt * 8 + tig * 2 + jx;
                    float v = s[mt][nt][c] * scale
                              - slope * fabsf((float)(qrow - kcol));
                    s[mt][nt][c] = v;
                    mx = fmaxf(mx, v);
                }
            mx = fmaxf(mx, __shfl_xor_sync(0xFFFFFFFFu, mx, 1));
            mx = fmaxf(mx, __shfl_xor_sync(0xFFFFFFFFu, mx, 2));
            float newm = fmaxf(m_run[rr], mx);
            corr[rr] = __expf(m_run[rr] - newm);
            m_run[rr] = newm;
            float ps = 0.f;
            #pragma unroll
            for (int nt = 0; nt < 8; nt++)
                #pragma unroll
                for (int jx = 0; jx < 2; jx++) {
                    int c = half * 2 + jx;
                    float p = __expf(s[mt][nt][c] - newm);
                    s[mt][nt][c] = p;
                    ps += p;
                }
            ps += __shfl_xor_sync(0xFFFFFFFFu, ps, 1);
            ps += __shfl_xor_sync(0xFFFFFFFFu, ps, 2);
            l_run[rr] = l_run[rr] * corr[rr] + ps;
        }
        #pragma unroll
        for (int mt = 0; mt < 2; mt++)
            #pragma unroll
            for (int nt = 0; nt < 6; nt++) {
                oacc[mt][nt][0] *= corr[mt*2];     oacc[mt][nt][1] *= corr[mt*2];
                oacc[mt][nt][2] *= corr[mt*2 + 1]; oacc[mt][nt][3] *= corr[mt*2 + 1];
            }

        // ---- O += P V (3-term split); P accum tiles fold into A frags ----
        #pragma unroll
        for (int ks2 = 0; ks2 < 4; ks2++) {
            uint32_t pah[2][4], pal[2][4];
            #pragma unroll
            for (int mt = 0; mt < 2; mt++)
                #pragma unroll
                for (int q2 = 0; q2 < 4; q2++) {
                    int nt = 2 * ks2 + (q2 >> 1);
                    int cb = (q2 & 1) * 2;
                    float v0 = s[mt][nt][cb], v1 = s[mt][nt][cb + 1];
                    bf162 H = __floats2bfloat162_rn(v0, v1);
                    float h0 = __bfloat162float(H.x), h1 = __bfloat162float(H.y);
                    bf162 L = __floats2bfloat162_rn(v0 - h0, v1 - h1);
                    pah[mt][q2] = *(uint32_t*)&H;
                    pal[mt][q2] = *(uint32_t*)&L;
                }
            uint32_t vh[6][2], vl[6][2];
            #pragma unroll
            for (int vt = 0; vt < 3; vt++) {
                int r = ks2 * 16 + (lane & 15);
                int c = vt * 2 + (lane >> 4);
                uint32_t off = (uint32_t)(r * 128 + ((c ^ (r & 3)) << 4));
                ldsm4t(vh[2*vt][0], vh[2*vt][1], vh[2*vt+1][0], vh[2*vt+1][1],
                       st + 16384 + off);
                ldsm4t(vl[2*vt][0], vl[2*vt][1], vl[2*vt+1][0], vl[2*vt+1][1],
                       st + 24576 + off);
            }
            #pragma unroll
            for (int mt = 0; mt < 2; mt++)
                #pragma unroll
                for (int nt = 0; nt < 6; nt++) {
                    mma16816(oacc[mt][nt], pah[mt], vh[nt]);
                    mma16816(oacc[mt][nt], pah[mt], vl[nt]);
                    mma16816(oacc[mt][nt], pal[mt], vh[nt]);
                }
        }
        __syncthreads();
    }

    // ---- epilogue: normalize + split store ----
    #pragma unroll
    for (int mt = 0; mt < 2; mt++) {
        float inv0 = 1.0f / l_run[mt*2];
        float inv1 = 1.0f / l_run[mt*2 + 1];
        size_t row0 = (rbase + wm + mt * 16 + grp) * DM + hh * HDIM + tig * 2;
        size_t row1 = row0 + 8 * DM;
        #pragma unroll
        for (int nt = 0; nt < 6; nt++) {
            float v00 = oacc[mt][nt][0] * inv0, v01 = oacc[mt][nt][1] * inv0;
            float v10 = oacc[mt][nt][2] * inv1, v11 = oacc[mt][nt][3] * inv1;
            bf16 h0, l0, h1, l1;
            split1(v00, h0, l0); split1(v01, h1, l1);
            bf162 H0; H0.x = h0; H0.y = h1;
            bf162 L0; L0.x = l0; L0.y = l1;
            *(bf162*)(out_hi + row0 + nt * 8) = H0;
            *(bf162*)(out_lo + row0 + nt * 8) = L0;
            split1(v10, h0, l0); split1(v11, h1, l1);
            bf162 H1; H1.x = h0; H1.y = h1;
            bf162 L1; L1.x = l0; L1.y = l1;
            *(bf162*)(out_hi + row1 + nt * 8) = H1;
            *(bf162*)(out_lo + row1 + nt * 8) = L1;
        }
    }
}

// ---------------- silu(gate)*up with fused bf16 split ------------------------
__global__ void silu_split_kernel(const float4* __restrict__ g,
                                  const float4* __restrict__ u,
                                  bf162* __restrict__ ohi, bf162* __restrict__ olo,
                                  int n4)
{
    int i = blockIdx.x * blockDim.x + threadIdx.x;
    if (i >= n4) return;
    float4 gv = g[i], uv = u[i];
    float y0 = uv.x * gv.x / (1.0f + __expf(-gv.x));
    float y1 = uv.y * gv.y / (1.0f + __expf(-gv.y));
    float y2 = uv.z * gv.z / (1.0f + __expf(-gv.z));
    float y3 = uv.w * gv.w / (1.0f + __expf(-gv.w));
    bf16 h0, l0, h1, l1, h2, l2, h3, l3;
    split1(y0, h0, l0); split1(y1, h1, l1);
    split1(y2, h2, l2); split1(y3, h3, l3);
    bf162 H0; H0.x = h0; H0.y = h1;
    bf162 H1; H1.x = h2; H1.y = h3;
    bf162 L0; L0.x = l0; L0.y = l1;
    bf162 L1; L1.x = l2; L1.y = l3;
    ohi[i * 2] = H0; ohi[i * 2 + 1] = H1;
    olo[i * 2] = L0; olo[i * 2 + 1] = L1;
}

// ---------------- host orchestration ----------------------------------------
static void run_gemm(int mode, const bf16* ah, const bf16* al,
                     const bf16* bh, const bf16* bl,
                     const float* cin, float* c, bf16* chi, bf16* clo,
                     int M, int N, int K)
{
    dim3 grid(N / 128, M / 128);
    if (mode == 0)
        mma_gemm_kernel<0><<<grid, 256, GEMM_SMEM>>>(ah, al, bh, bl, cin, c,
                                                     chi, clo, M, N, K);
    else if (mode == 1)
        mma_gemm_kernel<1><<<grid, 256, GEMM_SMEM>>>(ah, al, bh, bl, cin, c,
                                                     chi, clo, M, N, K);
    else
        mma_gemm_kernel<2><<<grid, 256, GEMM_SMEM>>>(ah, al, bh, bl, cin, c,
                                                     chi, clo, M, N, K);
}

extern "C" void kernel_launch(void* const* d_in, const int* in_sizes, int n_in,
                              void* d_out, int out_size)
{
    const float* cls_tokens = (const float*)d_in[0];
    const float* cls_token  = (const float*)d_in[1];
    const float* log_slopes = (const float*)d_in[2];
    const float* Wqkv       = (const float*)d_in[3];
    const float* Wo         = (const float*)d_in[4];
    const float* Wg         = (const float*)d_in[5];
    const float* Wu         = (const float*)d_in[6];
    const float* Wd         = (const float*)d_in[7];
    const float* ln1w       = (const float*)d_in[8];
    const float* ln1b       = (const float*)d_in[9];
    const float* ln2w       = (const float*)d_in[10];
    const float* ln2b       = (const float*)d_in[11];
    const float* finw       = (const float*)d_in[12];
    const float* finb       = (const float*)d_in[13];
    float* out = (float*)d_out;

    cudaFuncSetAttribute(mma_gemm_kernel<0>,
                         cudaFuncAttributeMaxDynamicSharedMemorySize, GEMM_SMEM);
    cudaFuncSetAttribute(mma_gemm_kernel<1>,
                         cudaFuncAttributeMaxDynamicSharedMemorySize, GEMM_SMEM);
    cudaFuncSetAttribute(mma_gemm_kernel<2>,
                         cudaFuncAttributeMaxDynamicSharedMemorySize, GEMM_SMEM);
    cudaFuncSetAttribute(flash_attn_mma_kernel,
                         cudaFuncAttributeMaxDynamicSharedMemorySize, ATT_SMEM);

    float *x, *gate, *up;
    bf16 *qkvh, *qkvl;
    bf16 *h_hi, *h_lo, *at_hi, *at_lo, *gg_hi, *gg_lo;
    bf16 *wqkv_hi, *wqkv_lo, *wo_hi, *wo_lo, *wg_hi, *wg_lo,
         *wu_hi, *wu_lo, *wd_hi, *wd_lo;
    cudaGetSymbolAddress((void**)&x,    g_x);
    cudaGetSymbolAddress((void**)&gate, g_gate);
    cudaGetSymbolAddress((void**)&up,   g_up);
    cudaGetSymbolAddress((void**)&qkvh, g_qkvh);
    cudaGetSymbolAddress((void**)&qkvl, g_qkvl);
    cudaGetSymbolAddress((void**)&h_hi, g_h_hi);
    cudaGetSymbolAddress((void**)&h_lo, g_h_lo);
    cudaGetSymbolAddress((void**)&at_hi, g_at_hi);
    cudaGetSymbolAddress((void**)&at_lo, g_at_lo);
    cudaGetSymbolAddress((void**)&gg_hi, g_g_hi);
    cudaGetSymbolAddress((void**)&gg_lo, g_g_lo);
    cudaGetSymbolAddress((void**)&wqkv_hi, g_wqkv_hi);
    cudaGetSymbolAddress((void**)&wqkv_lo, g_wqkv_lo);
    cudaGetSymbolAddress((void**)&wo_hi, g_wo_hi);
    cudaGetSymbolAddress((void**)&wo_lo, g_wo_lo);
    cudaGetSymbolAddress((void**)&wg_hi, g_wg_hi);
    cudaGetSymbolAddress((void**)&wg_lo, g_wg_lo);
    cudaGetSymbolAddress((void**)&wu_hi, g_wu_hi);
    cudaGetSymbolAddress((void**)&wu_lo, g_wu_lo);
    cudaGetSymbolAddress((void**)&wd_hi, g_wd_hi);
    cudaGetSymbolAddress((void**)&wd_lo, g_wd_lo);

    // weight conversion (fp32 -> bf16 hi/lo), once per launch
    {
        int n;
        n = LAYERS * 3 * DM * DM / 4;
        split4_kernel<<<(n + 255) / 256, 256>>>((const float4*)Wqkv,
            (bf162*)wqkv_hi, (bf162*)wqkv_lo, n);
        n = LAYERS * DM * DM / 4;
        split4_kernel<<<(n + 255) / 256, 256>>>((const float4*)Wo,
            (bf162*)wo_hi, (bf162*)wo_lo, n);
        n = LAYERS * FFDIM * DM / 4;
        split4_kernel<<<(n + 255) / 256, 256>>>((const float4*)Wg,
            (bf162*)wg_hi, (bf162*)wg_lo, n);
        split4_kernel<<<(n + 255) / 256, 256>>>((const float4*)Wu,
            (bf162*)wu_hi, (bf162*)wu_lo, n);
        n = LAYERS * DM * FFDIM / 4;
        split4_kernel<<<(n + 255) / 256, 256>>>((const float4*)Wd,
            (bf162*)wd_hi, (bf162*)wd_lo, n);
    }

    build_x_kernel<<<(MTOK * DM + 255) / 256, 256>>>(cls_tokens, cls_token, x);

    for (int l = 0; l < LAYERS; l++) {
        size_t oq = (size_t)l * 3 * DM * DM;
        size_t oo = (size_t)l * DM * DM;
        size_t og = (size_t)l * FFDIM * DM;
        size_t od = (size_t)l * DM * FFDIM;

        layernorm_split_kernel<<<MTOK, 256>>>(x, h_hi, h_lo,
                                              ln1w + l * DM, ln1b + l * DM);

        // QKV GEMM with split-bf16 epilogue (no fp32 qkv tensor)
        run_gemm(2, h_hi, h_lo, wqkv_hi + oq, wqkv_lo + oq,
                 nullptr, nullptr, qkvh, qkvl, MTOK, 3 * DM, DM);

        flash_attn_mma_kernel<<<dim3(SEQ / 128, NH, BATCH), 128, ATT_SMEM>>>(
            qkvh, qkvl, log_slopes, at_hi, at_lo);

        run_gemm(1, at_hi, at_lo, wo_hi + oo, wo_lo + oo,
                 x, x, nullptr, nullptr, MTOK, DM, DM);

        layernorm_split_kernel<<<MTOK, 256>>>(x, h_hi, h_lo,
                                              ln2w + l * DM, ln2b + l * DM);

        run_gemm(0, h_hi, h_lo, wg_hi + og, wg_lo + og,
                 nullptr, gate, nullptr, nullptr, MTOK, FFDIM, DM);
        run_gemm(0, h_hi, h_lo, wu_hi + og, wu_lo + og,
                 nullptr, up, nullptr, nullptr, MTOK, FFDIM, DM);

        int n4 = MTOK * FFDIM / 4;
        silu_split_kernel<<<(n4 + 255) / 256, 256>>>(
            (const float4*)gate, (const float4*)up,
            (bf162*)gg_hi, (bf162*)gg_lo, n4);

        run_gemm(1, gg_hi, gg_lo, wd_hi + od, wd_lo + od,
                 x, x, nullptr, nullptr, MTOK, DM, FFDIM);
    }

    layernorm_kernel<<<BATCH, 256>>>(x, (size_t)SEQ * DM, out, finw, finb);
}

// round 12
// speedup vs baseline: 2.6667x; 1.0087x over previous
#include <cuda_runtime.h>
#include <cuda_bf16.h>
#include <math.h>
#include <stdint.h>
#include <string.h>

// ---------------- problem constants ----------------
#define LAYERS 6
#define BATCH  4
#define SEQ    1024
#define DM     768
#define NH     16
#define HDIM   48
#define FFDIM  3072
#define MTOK   (BATCH*SEQ)   // 4096

typedef unsigned long long u64;
typedef __nv_bfloat16  bf16;
typedef __nv_bfloat162 bf162;

// ---------------- mma.sync / ldmatrix / cp.async helpers --------------------
__device__ __forceinline__ uint32_t smem_u32(const void* p) {
    uint32_t a;
    asm("{ .reg .u64 t; cvta.to.shared.u64 t, %1; cvt.u32.u64 %0, t; }"
        : "=r"(a) : "l"(p));
    return a;
}
__device__ __forceinline__ void cp16(uint32_t dst, const void* src) {
    asm volatile("cp.async.cg.shared.global [%0], [%1], 16;" :: "r"(dst), "l"(src));
}
#define CP_COMMIT() asm volatile("cp.async.commit_group;" ::: "memory")
#define CP_WAIT1()  asm volatile("cp.async.wait_group 1;" ::: "memory")
#define CP_WAIT0()  asm volatile("cp.async.wait_group 0;" ::: "memory")

__device__ __forceinline__ void ldsm4(uint32_t &r0, uint32_t &r1,
                                      uint32_t &r2, uint32_t &r3, uint32_t addr) {
    asm volatile("ldmatrix.sync.aligned.m8n8.x4.shared.b16 {%0,%1,%2,%3}, [%4];"
                 : "=r"(r0), "=r"(r1), "=r"(r2), "=r"(r3) : "r"(addr));
}
__device__ __forceinline__ void ldsm4t(uint32_t &r0, uint32_t &r1,
                                       uint32_t &r2, uint32_t &r3, uint32_t addr) {
    asm volatile("ldmatrix.sync.aligned.m8n8.x4.trans.shared.b16 {%0,%1,%2,%3}, [%4];"
                 : "=r"(r0), "=r"(r1), "=r"(r2), "=r"(r3) : "r"(addr));
}
__device__ __forceinline__ void mma16816(float* d, const uint32_t* a,
                                         const uint32_t* b) {
    asm volatile("mma.sync.aligned.m16n8k16.row.col.f32.bf16.bf16.f32 "
        "{%0,%1,%2,%3}, {%4,%5,%6,%7}, {%8,%9}, {%0,%1,%2,%3};"
        : "+f"(d[0]), "+f"(d[1]), "+f"(d[2]), "+f"(d[3])
        : "r"(a[0]), "r"(a[1]), "r"(a[2]), "r"(a[3]), "r"(b[0]), "r"(b[1]));
}

// ---------------- scratch (device globals) ----------------------------------
__device__ __align__(16) float g_x   [MTOK*DM];
__device__ __align__(16) float g_gate[MTOK*FFDIM];
__device__ __align__(16) float g_up  [MTOK*FFDIM];

__device__ __align__(16) bf16 g_qkvh[MTOK*3*DM];
__device__ __align__(16) bf16 g_qkvl[MTOK*3*DM];

__device__ __align__(16) bf16 g_h_hi [MTOK*DM];
__device__ __align__(16) bf16 g_h_lo [MTOK*DM];
__device__ __align__(16) bf16 g_at_hi[MTOK*DM];
__device__ __align__(16) bf16 g_at_lo[MTOK*DM];
__device__ __align__(16) bf16 g_g_hi [MTOK*FFDIM];
__device__ __align__(16) bf16 g_g_lo [MTOK*FFDIM];

__device__ __align__(16) bf16 g_wqkv_hi[LAYERS*3*DM*DM];
__device__ __align__(16) bf16 g_wqkv_lo[LAYERS*3*DM*DM];
__device__ __align__(16) bf16 g_wo_hi  [LAYERS*DM*DM];
__device__ __align__(16) bf16 g_wo_lo  [LAYERS*DM*DM];
__device__ __align__(16) bf16 g_wg_hi  [LAYERS*FFDIM*DM];
__device__ __align__(16) bf16 g_wg_lo  [LAYERS*FFDIM*DM];
__device__ __align__(16) bf16 g_wu_hi  [LAYERS*FFDIM*DM];
__device__ __align__(16) bf16 g_wu_lo  [LAYERS*FFDIM*DM];
__device__ __align__(16) bf16 g_wd_hi  [LAYERS*DM*FFDIM];
__device__ __align__(16) bf16 g_wd_lo  [LAYERS*DM*FFDIM];

// ---------------- split helpers ---------------------------------------------
__device__ __forceinline__ void split1(float x, bf16 &h, bf16 &l) {
    h = __float2bfloat16(x);
    l = __float2bfloat16(x - __bfloat162float(h));
}

__global__ void split4_kernel(const float4* __restrict__ in,
                              bf162* __restrict__ hi, bf162* __restrict__ lo,
                              int n4)
{
    int i = blockIdx.x * blockDim.x + threadIdx.x;
    if (i >= n4) return;
    float4 v = in[i];
    bf16 h0, l0, h1, l1, h2, l2, h3, l3;
    split1(v.x, h0, l0); split1(v.y, h1, l1);
    split1(v.z, h2, l2); split1(v.w, h3, l3);
    bf162 H0; H0.x = h0; H0.y = h1;
    bf162 H1; H1.x = h2; H1.y = h3;
    bf162 L0; L0.x = l0; L0.y = l1;
    bf162 L1; L1.x = l2; L1.y = l3;
    hi[i * 2] = H0; hi[i * 2 + 1] = H1;
    lo[i * 2] = L0; lo[i * 2 + 1] = L1;
}

// ---------------- build x ----------------------------------------------------
__global__ void build_x_kernel(const float* __restrict__ cls_tokens,
                               const float* __restrict__ cls_token,
                               float* __restrict__ x)
{
    int idx = blockIdx.x * blockDim.x + threadIdx.x;
    if (idx >= MTOK * DM) return;
    int row = idx / DM;
    int d   = idx - row * DM;
    int b   = row >> 10;
    int s   = row & (SEQ - 1);
    float v;
    if (s == 0) v = cls_token[d];
    else        v = cls_tokens[((b * (SEQ - 1)) + (s - 1)) * DM + d];
    x[idx] = v;
}

// ---------------- layernorm (fp32 out) ---------------------------------------
__global__ __launch_bounds__(256) void layernorm_kernel(
    const float* __restrict__ in, size_t in_stride, float* __restrict__ out,
    const float* __restrict__ w, const float* __restrict__ b)
{
    int row = blockIdx.x;
    const float* xr = in + (size_t)row * in_stride;
    int t = threadIdx.x;
    float v0 = xr[t], v1 = xr[t + 256], v2 = xr[t + 512];
    float s  = v0 + v1 + v2;
    float sq = v0 * v0 + v1 * v1 + v2 * v2;
    #pragma unroll
    for (int o = 16; o > 0; o >>= 1) {
        s  += __shfl_xor_sync(0xFFFFFFFFu, s,  o);
        sq += __shfl_xor_sync(0xFFFFFFFFu, sq, o);
    }
    __shared__ float ss[8], sqs[8];
    int wid = t >> 5, lane = t & 31;
    if (lane == 0) { ss[wid] = s; sqs[wid] = sq; }
    __syncthreads();
    float ts = 0.f, tq = 0.f;
    #pragma unroll
    for (int i = 0; i < 8; i++) { ts += ss[i]; tq += sqs[i]; }
    float mean = ts * (1.0f / DM);
    float var  = tq * (1.0f / DM) - mean * mean;
    float rstd = rsqrtf(var + 1e-5f);
    float* orow = out + (size_t)row * DM;
    orow[t]       = (v0 - mean) * rstd * w[t]       + b[t];
    orow[t + 256] = (v1 - mean) * rstd * w[t + 256] + b[t + 256];
    orow[t + 512] = (v2 - mean) * rstd * w[t + 512] + b[t + 512];
}

// ---------------- layernorm with fused bf16 hi/lo split ----------------------
__global__ __launch_bounds__(256) void layernorm_split_kernel(
    const float* __restrict__ in, bf16* __restrict__ ohi, bf16* __restrict__ olo,
    const float* __restrict__ w, const float* __restrict__ b)
{
    int row = blockIdx.x;
    const float* xr = in + (size_t)row * DM;
    int t = threadIdx.x;
    float v0 = xr[t], v1 = xr[t + 256], v2 = xr[t + 512];
    float s  = v0 + v1 + v2;
    float sq = v0 * v0 + v1 * v1 + v2 * v2;
    #pragma unroll
    for (int o = 16; o > 0; o >>= 1) {
        s  += __shfl_xor_sync(0xFFFFFFFFu, s,  o);
        sq += __shfl_xor_sync(0xFFFFFFFFu, sq, o);
    }
    __shared__ float ss[8], sqs[8];
    int wid = t >> 5, lane = t & 31;
    if (lane == 0) { ss[wid] = s; sqs[wid] = sq; }
    __syncthreads();
    float ts = 0.f, tq = 0.f;
    #pragma unroll
    for (int i = 0; i < 8; i++) { ts += ss[i]; tq += sqs[i]; }
    float mean = ts * (1.0f / DM);
    float var  = tq * (1.0f / DM) - mean * mean;
    float rstd = rsqrtf(var + 1e-5f);
    size_t base = (size_t)row * DM;
    #pragma unroll
    for (int j = 0; j < 3; j++) {
        float v = (j == 0 ? v0 : (j == 1 ? v1 : v2));
        float y = (v - mean) * rstd * w[t + j * 256] + b[t + j * 256];
        bf16 h, l; split1(y, h, l);
        ohi[base + t + j * 256] = h;
        olo[base + t + j * 256] = l;
    }
}

// ---------------- fused 3-term HMMA bf16 split GEMM (BK=64, 2-stage) ---------
// EPI_MODE: 0 = store fp32, 1 = add Cin + store fp32, 2 = split-store bf16 hi/lo
// Stage = 4 tiles (Ah,Al,Bh,Bl) of 128x64 bf16 (16KB, 128B swizzled rows).
// 4 inner 16-k steps per stage -> half the syncs of the BK=32 version.
#define GSTAGE 65536
#define GEMM_SMEM (2 * GSTAGE)
template <int EPI_MODE>
__global__ __launch_bounds__(256) void mma_gemm_kernel(
    const bf16* __restrict__ Ah, const bf16* __restrict__ Al,
    const bf16* __restrict__ Bh, const bf16* __restrict__ Bl,
    const float* __restrict__ Cin, float* __restrict__ C,
    bf16* __restrict__ Chi, bf16* __restrict__ Clo,
    int M, int N, int K)
{
    extern __shared__ __align__(16) char dynsmem[];
    uint32_t sS = smem_u32(dynsmem);

    int tid = threadIdx.x, wid = tid >> 5, lane = tid & 31;
    int bm = blockIdx.y * 128, bn = blockIdx.x * 128;
    int wm = (wid & 1) * 64;
    int wn = (wid >> 1) * 32;

    float acc[4][4][4];
    #pragma unroll
    for (int i = 0; i < 4; i++)
        #pragma unroll
        for (int j = 0; j < 4; j++)
            #pragma unroll
            for (int q = 0; q < 4; q++) acc[i][j][q] = 0.f;

    const int T = K >> 6;           // stages of 64 k

    // copy geometry: per tile 1024 16B-chunks (128 rows x 8), 4 per thread
    int rC = tid >> 1;              // 0..127
    int cC = (tid & 1) * 4;         // 0 or 4 (16B-chunk col)

    auto issue = [&](int t) {
        int k0 = t << 6;
        uint32_t st = sS + (uint32_t)((t & 1) * GSTAGE);
        size_t ao = (size_t)(bm + rC) * K + k0 + cC * 8;
        size_t bo = (size_t)(bn + rC) * K + k0 + cC * 8;
        uint32_t rbase = (uint32_t)(rC * 128);
        #pragma unroll
        for (int i = 0; i < 4; i++) {
            uint32_t sw = rbase + (uint32_t)(((cC + i) ^ (rC & 7)) << 4);
            cp16(st + sw,          Ah + ao + i * 8);
            cp16(st + 16384 + sw,  Al + ao + i * 8);
            cp16(st + 32768 + sw,  Bh + bo + i * 8);
            cp16(st + 49152 + sw,  Bl + bo + i * 8);
        }
        CP_COMMIT();
    };

    issue(0);
    for (int t = 0; t < T; t++) {
        if (t + 1 < T) { issue(t + 1); CP_WAIT1(); }
        else          { CP_WAIT0(); }
        __syncthreads();

        uint32_t st = sS + (uint32_t)((t & 1) * GSTAGE);

        #pragma unroll
        for (int ks = 0; ks < 4; ks++) {
            uint32_t aH[4][4], aL[4][4];
            #pragma unroll
            for (int mt = 0; mt < 4; mt++) {
                int row = wm + mt * 16 + (lane & 15);
                int c = ks * 2 + (lane >> 4);
                uint32_t off = (uint32_t)(row * 128 + ((c ^ (row & 7)) << 4));
                ldsm4(aH[mt][0], aH[mt][1], aH[mt][2], aH[mt][3], st + off);
                ldsm4(aL[mt][0], aL[mt][1], aL[mt][2], aL[mt][3], st + 16384 + off);
            }
            uint32_t bH[4][2], bL[4][2];
            #pragma unroll
            for (int p = 0; p < 2; p++) {
                int n = wn + p * 16 + (lane & 7) + ((lane >> 4) << 3);
                int c = ks * 2 + ((lane >> 3) & 1);
                uint32_t off = (uint32_t)(n * 128 + ((c ^ (n & 7)) << 4));
                ldsm4(bH[2 * p][0], bH[2 * p][1], bH[2 * p + 1][0], bH[2 * p + 1][1],
                      st + 32768 + off);
                ldsm4(bL[2 * p][0], bL[2 * p][1], bL[2 * p + 1][0], bL[2 * p + 1][1],
                      st + 49152 + off);
            }
            #pragma unroll
            for (int mt = 0; mt < 4; mt++)
                #pragma unroll
                for (int nt = 0; nt < 4; nt++) {
                    mma16816(acc[mt][nt], aH[mt], bH[nt]);
                    mma16816(acc[mt][nt], aH[mt], bL[nt]);
                    mma16816(acc[mt][nt], aL[mt], bH[nt]);
                }
        }
        __syncthreads();
    }

    int grp = lane >> 2, tig = lane & 3;
    #pragma unroll
    for (int mt = 0; mt < 4; mt++) {
        #pragma unroll
        for (int nt = 0; nt < 4; nt++) {
            int row = bm + wm + mt * 16 + grp;
            int col = bn + wn + nt * 8 + tig * 2;
            size_t o0 = (size_t)row * N + col;
            size_t o1 = (size_t)(row + 8) * N + col;
            float2 v0, v1;
            v0.x = acc[mt][nt][0]; v0.y = acc[mt][nt][1];
            v1.x = acc[mt][nt][2]; v1.y = acc[mt][nt][3];
            if (EPI_MODE == 1) {
                float2 c0 = *(const float2*)&Cin[o0];
                float2 c1 = *(const float2*)&Cin[o1];
                v0.x += c0.x; v0.y += c0.y;
                v1.x += c1.x; v1.y += c1.y;
            }
            if (EPI_MODE == 2) {
                bf16 h0, l0, h1, l1;
                split1(v0.x, h0, l0); split1(v0.y, h1, l1);
                bf162 H0; H0.x = h0; H0.y = h1;
                bf162 L0; L0.x = l0; L0.y = l1;
                *(bf162*)(Chi + o0) = H0;
                *(bf162*)(Clo + o0) = L0;
                split1(v1.x, h0, l0); split1(v1.y, h1, l1);
                bf162 H1; H1.x = h0; H1.y = h1;
                bf162 L1; L1.x = l0; L1.y = l1;
                *(bf162*)(Chi + o1) = H1;
                *(bf162*)(Clo + o1) = L1;
            } else {
                *(float2*)&C[o0] = v0;
                *(float2*)&C[o1] = v1;
            }
        }
    }
}

// ---------------- HMMA flash attention (split bf16, ALiBi) -------------------
#define ATT_SMEM 65536
__global__ __launch_bounds__(128) void flash_attn_mma_kernel(
    const bf16* __restrict__ qkh, const bf16* __restrict__ qkl,
    const float* __restrict__ log_slopes,
    bf16* __restrict__ out_hi, bf16* __restrict__ out_lo)
{
    extern __shared__ __align__(16) char asmem[];
    uint32_t sb = smem_u32(asmem);
    const int QW = 3 * DM;
    int qt = blockIdx.x, hh = blockIdx.y, b = blockIdx.z;
    int tid = threadIdx.x, wid = tid >> 5, lane = tid & 31;
    int wm = wid * 32;
    int grp = lane >> 2, tig = lane & 3;
    float slope = __expf(log_slopes[hh]);
    const float scale = 0.14433756729740643f;  // 1/sqrt(48)
    size_t rbase = (size_t)(b * SEQ + qt * 128);

    #pragma unroll
    for (int i = 0; i < 6; i++) {
        int j = i * 128 + tid;
        int r = j / 6, c = j - r * 6;
        uint32_t dst = (uint32_t)(r * 128 + ((c ^ (r & 3)) << 4));
        size_t g = (rbase + r) * QW + hh * HDIM + c * 8;
        cp16(sb + dst, qkh + g);
        cp16(sb + 16384 + dst, qkl + g);
    }
    CP_COMMIT(); CP_WAIT0();
    __syncthreads();

    uint32_t qfh[2][3][4], qfl[2][3][4];
    #pragma unroll
    for (int mt = 0; mt < 2; mt++)
        #pragma unroll
        for (int ks = 0; ks < 3; ks++) {
            int r = wm + mt * 16 + (lane & 15);
            int c = ks * 2 + (lane >> 4);
            uint32_t off = (uint32_t)(r * 128 + ((c ^ (r & 3)) << 4));
            ldsm4(qfh[mt][ks][0], qfh[mt][ks][1], qfh[mt][ks][2], qfh[mt][ks][3],
                  sb + off);
            ldsm4(qfl[mt][ks][0], qfl[mt][ks][1], qfl[mt][ks][2], qfl[mt][ks][3],
                  sb + 16384 + off);
        }
    __syncthreads();

    float oacc[2][6][4];
    #pragma unroll
    for (int mt = 0; mt < 2; mt++)
        #pragma unroll
        for (int nt = 0; nt < 6; nt++)
            #pragma unroll
            for (int q = 0; q < 4; q++) oacc[mt][nt][q] = 0.f;
    float m_run[4], l_run[4];
    #pragma unroll
    for (int rr = 0; rr < 4; rr++) { m_run[rr] = -INFINITY; l_run[rr] = 0.f; }

    auto issueKV = [&](int kt) {
        uint32_t st = sb + (uint32_t)((kt & 1) * 32768);
        #pragma unroll
        for (int i = 0; i < 12; i++) {
            int j = i * 128 + tid;
            int mat = j / 384;
            int rem = j - mat * 384;
            int rr = rem / 6;
            int cc = rem - rr * 6;
            uint32_t dst = st + (uint32_t)(mat * 8192)
                         + (uint32_t)(rr * 128 + ((cc ^ (rr & 3)) << 4));
            size_t g = (size_t)(b * SEQ + kt * 64 + rr) * QW + hh * HDIM
                     + ((mat < 2) ? DM : 2 * DM) + cc * 8;
            const bf16* src = (mat & 1) ? qkl : qkh;
            cp16(dst, src + g);
        }
        CP_COMMIT();
    };

    issueKV(0);
    for (int kt = 0; kt < SEQ / 64; kt++) {
        if (kt + 1 < SEQ / 64) { issueKV(kt + 1); CP_WAIT1(); }
        else                   { CP_WAIT0(); }
        __syncthreads();
        uint32_t st = sb + (uint32_t)((kt & 1) * 32768);

        float s[2][8][4];
        #pragma unroll
        for (int mt = 0; mt < 2; mt++)
            #pragma unroll
            for (int nt = 0; nt < 8; nt++)
                #pragma unroll
                for (int q = 0; q < 4; q++) s[mt][nt][q] = 0.f;

        #pragma unroll
        for (int ks = 0; ks < 3; ks++) {
            uint32_t bh[8][2], bl[8][2];
            #pragma unroll
            for (int p = 0; p < 4; p++) {
                int n = p * 16 + (lane & 7) + ((lane >> 4) << 3);
                int c = ks * 2 + ((lane >> 3) & 1);
                uint32_t off = (uint32_t)(n * 128 + ((c ^ (n & 3)) << 4));
                ldsm4(bh[2*p][0], bh[2*p][1], bh[2*p+1][0], bh[2*p+1][1], st + off);
                ldsm4(bl[2*p][0], bl[2*p][1], bl[2*p+1][0], bl[2*p+1][1], st + 8192 + off);
            }
            #pragma unroll
            for (int mt = 0; mt < 2; mt++)
                #pragma unroll
                for (int nt = 0; nt < 8; nt++) {
                    mma16816(s[mt][nt], qfh[mt][ks], bh[nt]);
                    mma16816(s[mt][nt], qfh[mt][ks], bl[nt]);
                    mma16816(s[mt][nt], qfl[mt][ks], bh[nt]);
                }
        }

        float corr[4];
        #pragma unroll
        for (int rr = 0; rr < 4; rr++) {
            int mt = rr >> 1, half = rr & 1;
            int qrow = qt * 128 + wm + mt * 16 + half * 8 + grp;
            float mx = -INFINITY;
            #pragma unroll
            for (int nt = 0; nt < 8; nt++)
                #pragma unroll
                for (int jx = 0; jx < 2; jx++) {
                    int c = half * 2 + jx;
                    int kcol = kt * 64 + nt * 8 + tig * 2 + jx;
                    float v = s[mt][nt][c] * scale
                              - slope * fabsf((float)(qrow - kcol));
                    s[mt][nt][c] = v;
                    mx = fmaxf(mx, v);
                }
            mx = fmaxf(mx, __shfl_xor_sync(0xFFFFFFFFu, mx, 1));
            mx = fmaxf(mx, __shfl_xor_sync(0xFFFFFFFFu, mx, 2));
            float newm = fmaxf(m_run[rr], mx);
            corr[rr] = __expf(m_run[rr] - newm);
            m_run[rr] = newm;
            float ps = 0.f;
            #pragma unroll
            for (int nt = 0; nt < 8; nt++)
                #pragma unroll
                for (int jx = 0; jx < 2; jx++) {
                    int c = half * 2 + jx;
                    float p = __expf(s[mt][nt][c] - newm);
                    s[mt][nt][c] = p;
                    ps += p;
                }
            ps += __shfl_xor_sync(0xFFFFFFFFu, ps, 1);
            ps += __shfl_xor_sync(0xFFFFFFFFu, ps, 2);
            l_run[rr] = l_run[rr] * corr[rr] + ps;
        }
        #pragma unroll
        for (int mt = 0; mt < 2; mt++)
            #pragma unroll
            for (int nt = 0; nt < 6; nt++) {
                oacc[mt][nt][0] *= corr[mt*2];     oacc[mt][nt][1] *= corr[mt*2];
                oacc[mt][nt][2] *= corr[mt*2 + 1]; oacc[mt][nt][3] *= corr[mt*2 + 1];
            }

        #pragma unroll
        for (int ks2 = 0; ks2 < 4; ks2++) {
            uint32_t pah[2][4], pal[2][4];
            #pragma unroll
            for (int mt = 0; mt < 2; mt++)
                #pragma unroll
                for (int q2 = 0; q2 < 4; q2++) {
                    int nt = 2 * ks2 + (q2 >> 1);
                    int cb = (q2 & 1) * 2;
                    float v0 = s[mt][nt][cb], v1 = s[mt][nt][cb + 1];
                    bf162 H = __floats2bfloat162_rn(v0, v1);
                    float h0 = __bfloat162float(H.x), h1 = __bfloat162float(H.y);
                    bf162 L = __floats2bfloat162_rn(v0 - h0, v1 - h1);
                    pah[mt][q2] = *(uint32_t*)&H;
                    pal[mt][q2] = *(uint32_t*)&L;
                }
            uint32_t vh[6][2], vl[6][2];
            #pragma unroll
            for (int vt = 0; vt < 3; vt++) {
                int r = ks2 * 16 + (lane & 15);
                int c = vt * 2 + (lane >> 4);
                uint32_t off = (uint32_t)(r * 128 + ((c ^ (r & 3)) << 4));
                ldsm4t(vh[2*vt][0], vh[2*vt][1], vh[2*vt+1][0], vh[2*vt+1][1],
                       st + 16384 + off);
                ldsm4t(vl[2*vt][0], vl[2*vt][1], vl[2*vt+1][0], vl[2*vt+1][1],
                       st + 24576 + off);
            }
            #pragma unroll
            for (int mt = 0; mt < 2; mt++)
                #pragma unroll
                for (int nt = 0; nt < 6; nt++) {
                    mma16816(oacc[mt][nt], pah[mt], vh[nt]);
                    mma16816(oacc[mt][nt], pah[mt], vl[nt]);
                    mma16816(oacc[mt][nt], pal[mt], vh[nt]);
                }
        }
        __syncthreads();
    }

    #pragma unroll
    for (int mt = 0; mt < 2; mt++) {
        float inv0 = 1.0f / l_run[mt*2];
        float inv1 = 1.0f / l_run[mt*2 + 1];
        size_t row0 = (rbase + wm + mt * 16 + grp) * DM + hh * HDIM + tig * 2;
        size_t row1 = row0 + 8 * DM;
        #pragma unroll
        for (int nt = 0; nt < 6; nt++) {
            float v00 = oacc[mt][nt][0] * inv0, v01 = oacc[mt][nt][1] * inv0;
            float v10 = oacc[mt][nt][2] * inv1, v11 = oacc[mt][nt][3] * inv1;
            bf16 h0, l0, h1, l1;
            split1(v00, h0, l0); split1(v01, h1, l1);
            bf162 H0; H0.x = h0; H0.y = h1;
            bf162 L0; L0.x = l0; L0.y = l1;
            *(bf162*)(out_hi + row0 + nt * 8) = H0;
            *(bf162*)(out_lo + row0 + nt * 8) = L0;
            split1(v10, h0, l0); split1(v11, h1, l1);
            bf162 H1; H1.x = h0; H1.y = h1;
            bf162 L1; L1.x = l0; L1.y = l1;
            *(bf162*)(out_hi + row1 + nt * 8) = H1;
            *(bf162*)(out_lo + row1 + nt * 8) = L1;
        }
    }
}

// ---------------- silu(gate)*up with fused bf16 split ------------------------
__global__ void silu_split_kernel(const float4* __restrict__ g,
                                  const float4* __restrict__ u,
                                  bf162* __restrict__ ohi, bf162* __restrict__ olo,
                                  int n4)
{
    int i = blockIdx.x * blockDim.x + threadIdx.x;
    if (i >= n4) return;
    float4 gv = g[i], uv = u[i];
    float y0 = uv.x * gv.x / (1.0f + __expf(-gv.x));
    float y1 = uv.y * gv.y / (1.0f + __expf(-gv.y));
    float y2 = uv.z * gv.z / (1.0f + __expf(-gv.z));
    float y3 = uv.w * gv.w / (1.0f + __expf(-gv.w));
    bf16 h0, l0, h1, l1, h2, l2, h3, l3;
    split1(y0, h0, l0); split1(y1, h1, l1);
    split1(y2, h2, l2); split1(y3, h3, l3);
    bf162 H0; H0.x = h0; H0.y = h1;
    bf162 H1; H1.x = h2; H1.y = h3;
    bf162 L0; L0.x = l0; L0.y = l1;
    bf162 L1; L1.x = l2; L1.y = l3;
    ohi[i * 2] = H0; ohi[i * 2 + 1] = H1;
    olo[i * 2] = L0; olo[i * 2 + 1] = L1;
}

// ---------------- host orchestration ----------------------------------------
static void run_gemm(int mode, const bf16* ah, const bf16* al,
                     const bf16* bh, const bf16* bl,
                     const float* cin, float* c, bf16* chi, bf16* clo,
                     int M, int N, int K)
{
    dim3 grid(N / 128, M / 128);
    if (mode == 0)
        mma_gemm_kernel<0><<<grid, 256, GEMM_SMEM>>>(ah, al, bh, bl, cin, c,
                                                     chi, clo, M, N, K);
    else if (mode == 1)
        mma_gemm_kernel<1><<<grid, 256, GEMM_SMEM>>>(ah, al, bh, bl, cin, c,
                                                     chi, clo, M, N, K);
    else
        mma_gemm_kernel<2><<<grid, 256, GEMM_SMEM>>>(ah, al, bh, bl, cin, c,
                                                     chi, clo, M, N, K);
}

extern "C" void kernel_launch(void* const* d_in, const int* in_sizes, int n_in,
                              void* d_out, int out_size)
{
    const float* cls_tokens = (const float*)d_in[0];
    const float* cls_token  = (const float*)d_in[1];
    const float* log_slopes = (const float*)d_in[2];
    const float* Wqkv       = (const float*)d_in[3];
    const float* Wo         = (const float*)d_in[4];
    const float* Wg         = (const float*)d_in[5];
    const float* Wu         = (const float*)d_in[6];
    const float* Wd         = (const float*)d_in[7];
    const float* ln1w       = (const float*)d_in[8];
    const float* ln1b       = (const float*)d_in[9];
    const float* ln2w       = (const float*)d_in[10];
    const float* ln2b       = (const float*)d_in[11];
    const float* finw       = (const float*)d_in[12];
    const float* finb       = (const float*)d_in[13];
    float* out = (float*)d_out;

    cudaFuncSetAttribute(mma_gemm_kernel<0>,
                         cudaFuncAttributeMaxDynamicSharedMemorySize, GEMM_SMEM);
    cudaFuncSetAttribute(mma_gemm_kernel<1>,
                         cudaFuncAttributeMaxDynamicSharedMemorySize, GEMM_SMEM);
    cudaFuncSetAttribute(mma_gemm_kernel<2>,
                         cudaFuncAttributeMaxDynamicSharedMemorySize, GEMM_SMEM);
    cudaFuncSetAttribute(flash_attn_mma_kernel,
                         cudaFuncAttributeMaxDynamicSharedMemorySize, ATT_SMEM);

    float *x, *gate, *up;
    bf16 *qkvh, *qkvl;
    bf16 *h_hi, *h_lo, *at_hi, *at_lo, *gg_hi, *gg_lo;
    bf16 *wqkv_hi, *wqkv_lo, *wo_hi, *wo_lo, *wg_hi, *wg_lo,
         *wu_hi, *wu_lo, *wd_hi, *wd_lo;
    cudaGetSymbolAddress((void**)&x,    g_x);
    cudaGetSymbolAddress((void**)&gate, g_gate);
    cudaGetSymbolAddress((void**)&up,   g_up);
    cudaGetSymbolAddress((void**)&qkvh, g_qkvh);
    cudaGetSymbolAddress((void**)&qkvl, g_qkvl);
    cudaGetSymbolAddress((void**)&h_hi, g_h_hi);
    cudaGetSymbolAddress((void**)&h_lo, g_h_lo);
    cudaGetSymbolAddress((void**)&at_hi, g_at_hi);
    cudaGetSymbolAddress((void**)&at_lo, g_at_lo);
    cudaGetSymbolAddress((void**)&gg_hi, g_g_hi);
    cudaGetSymbolAddress((void**)&gg_lo, g_g_lo);
    cudaGetSymbolAddress((void**)&wqkv_hi, g_wqkv_hi);
    cudaGetSymbolAddress((void**)&wqkv_lo, g_wqkv_lo);
    cudaGetSymbolAddress((void**)&wo_hi, g_wo_hi);
    cudaGetSymbolAddress((void**)&wo_lo, g_wo_lo);
    cudaGetSymbolAddress((void**)&wg_hi, g_wg_hi);
    cudaGetSymbolAddress((void**)&wg_lo, g_wg_lo);
    cudaGetSymbolAddress((void**)&wu_hi, g_wu_hi);
    cudaGetSymbolAddress((void**)&wu_lo, g_wu_lo);
    cudaGetSymbolAddress((void**)&wd_hi, g_wd_hi);
    cudaGetSymbolAddress((void**)&wd_lo, g_wd_lo);

    // weight conversion (fp32 -> bf16 hi/lo), once per launch
    {
        int n;
        n = LAYERS * 3 * DM * DM / 4;
        split4_kernel<<<(n + 255) / 256, 256>>>((const float4*)Wqkv,
            (bf162*)wqkv_hi, (bf162*)wqkv_lo, n);
        n = LAYERS * DM * DM / 4;
        split4_kernel<<<(n + 255) / 256, 256>>>((const float4*)Wo,
            (bf162*)wo_hi, (bf162*)wo_lo, n);
        n = LAYERS * FFDIM * DM / 4;
        split4_kernel<<<(n + 255) / 256, 256>>>((const float4*)Wg,
            (bf162*)wg_hi, (bf162*)wg_lo, n);
        split4_kernel<<<(n + 255) / 256, 256>>>((const float4*)Wu,
            (bf162*)wu_hi, (bf162*)wu_lo, n);
        n = LAYERS * DM * FFDIM / 4;
        split4_kernel<<<(n + 255) / 256, 256>>>((const float4*)Wd,
            (bf162*)wd_hi, (bf162*)wd_lo, n);
    }

    build_x_kernel<<<(MTOK * DM + 255) / 256, 256>>>(cls_tokens, cls_token, x);

    for (int l = 0; l < LAYERS; l++) {
        size_t oq = (size_t)l * 3 * DM * DM;
        size_t oo = (size_t)l * DM * DM;
        size_t og = (size_t)l * FFDIM * DM;
        size_t od = (size_t)l * DM * FFDIM;

        layernorm_split_kernel<<<MTOK, 256>>>(x, h_hi, h_lo,
                                              ln1w + l * DM, ln1b + l * DM);

        run_gemm(2, h_hi, h_lo, wqkv_hi + oq, wqkv_lo + oq,
                 nullptr, nullptr, qkvh, qkvl, MTOK, 3 * DM, DM);

        flash_attn_mma_kernel<<<dim3(SEQ / 128, NH, BATCH), 128, ATT_SMEM>>>(
            qkvh, qkvl, log_slopes, at_hi, at_lo);

        run_gemm(1, at_hi, at_lo, wo_hi + oo, wo_lo + oo,
                 x, x, nullptr, nullptr, MTOK, DM, DM);

        layernorm_split_kernel<<<MTOK, 256>>>(x, h_hi, h_lo,
                                              ln2w + l * DM, ln2b + l * DM);

        run_gemm(0, h_hi, h_lo, wg_hi + og, wg_lo + og,
                 nullptr, gate, nullptr, nullptr, MTOK, FFDIM, DM);
        run_gemm(0, h_hi, h_lo, wu_hi + og, wu_lo + og,
                 nullptr, up, nullptr, nullptr, MTOK, FFDIM, DM);

        int n4 = MTOK * FFDIM / 4;
        silu_split_kernel<<<(n4 + 255) / 256, 256>>>(
            (const float4*)gate, (const float4*)up,
            (bf162*)gg_hi, (bf162*)gg_lo, n4);

        run_gemm(1, gg_hi, gg_lo, wd_hi + od, wd_lo + od,
                 x, x, nullptr, nullptr, MTOK, DM, FFDIM);
    }

    layernorm_kernel<<<BATCH, 256>>>(x, (size_t)SEQ * DM, out, finw, finb);
}